// round 1
// baseline (speedup 1.0000x reference)
#include <cuda_runtime.h>

#define B_ 64
#define T_ 256
#define C_ 384
#define H_ 6
#define D_ 64
#define M_ (B_*T_)

// Scratch (allocation-free rule: __device__ globals)
__device__ float g_q[B_*H_*T_*D_];
__device__ float g_k[B_*H_*T_*D_];
__device__ float g_v[B_*H_*T_*D_];
__device__ float g_o[B_*H_*T_*D_];

// ---------------------------------------------------------------------------
// Kernel 1: QKV projection. For (mat, head): Y[16384, 64] = X[16384,384] @ W[384,64]
// Output layout [B, H, T, D].
// ---------------------------------------------------------------------------
__global__ __launch_bounds__(256) void qkv_kernel(const float* __restrict__ x,
                                                  const float* __restrict__ Wq,
                                                  const float* __restrict__ Wk,
                                                  const float* __restrict__ Wv) {
    const int mat = blockIdx.y / H_;
    const int h   = blockIdx.y % H_;
    const float* W = (mat == 0 ? Wq : (mat == 1 ? Wk : Wv)) + h * C_ * D_;
    float* outp    = (mat == 0 ? g_q : (mat == 1 ? g_k : g_v));
    const int m0 = blockIdx.x * 64;

    __shared__ float As[16][64];   // [k][m]
    __shared__ float Bs[16][68];   // [k][n] (+4 pad)

    const int tid = threadIdx.x;
    const int ty = tid >> 4, tx = tid & 15;

    float acc[4][4];
#pragma unroll
    for (int i = 0; i < 4; i++)
#pragma unroll
        for (int j = 0; j < 4; j++) acc[i][j] = 0.f;

    for (int k0 = 0; k0 < C_; k0 += 16) {
#pragma unroll
        for (int i = 0; i < 4; i++) {
            int e = tid + i * 256;
            int r = e >> 4, c = e & 15;
            As[c][r] = x[(m0 + r) * C_ + k0 + c];
        }
#pragma unroll
        for (int i = 0; i < 4; i++) {
            int e = tid + i * 256;
            int r = e >> 6, c = e & 63;
            Bs[r][c] = W[(k0 + r) * D_ + c];
        }
        __syncthreads();
#pragma unroll
        for (int k = 0; k < 16; k++) {
            float a[4], b[4];
#pragma unroll
            for (int i = 0; i < 4; i++) a[i] = As[k][ty * 4 + i];
#pragma unroll
            for (int j = 0; j < 4; j++) b[j] = Bs[k][tx * 4 + j];
#pragma unroll
            for (int i = 0; i < 4; i++)
#pragma unroll
                for (int j = 0; j < 4; j++) acc[i][j] += a[i] * b[j];
        }
        __syncthreads();
    }

#pragma unroll
    for (int i = 0; i < 4; i++) {
        int m = m0 + ty * 4 + i;
        int bb = m / T_, t = m % T_;
        float* op = &outp[((bb * H_ + h) * T_ + t) * D_ + tx * 4];
#pragma unroll
        for (int j = 0; j < 4; j++) op[j] = acc[i][j];
    }
}

// ---------------------------------------------------------------------------
// Kernel 2: causal attention, flash-style. One CTA per (b, h, 64-row q tile).
// smem: Q tile, K/V tile (shared buffer), S tile, m/l/corr rows.
// ---------------------------------------------------------------------------
#define LDS_ 65
#define ATTN_SMEM_FLOATS (3 * 64 * LDS_ + 3 * 64)
#define ATTN_SMEM_BYTES  (ATTN_SMEM_FLOATS * 4)

__global__ __launch_bounds__(256) void attn_kernel() {
    extern __shared__ float sm[];
    float* Qs   = sm;                   // 64 x LDS_
    float* KVs  = Qs + 64 * LDS_;       // 64 x LDS_ (K, then reused for V)
    float* Ss   = KVs + 64 * LDS_;      // 64 x LDS_
    float* mrow = Ss + 64 * LDS_;       // 64
    float* lrow = mrow + 64;            // 64
    float* crow = lrow + 64;            // 64

    const int qb = blockIdx.x;          // q tile (0..3)
    const int h  = blockIdx.y;
    const int b  = blockIdx.z;
    const float* qp = g_q + (size_t)((b * H_ + h) * T_) * D_;
    const float* kp = g_k + (size_t)((b * H_ + h) * T_) * D_;
    const float* vp = g_v + (size_t)((b * H_ + h) * T_) * D_;

    const int tid = threadIdx.x;
    const int ty = tid >> 4, tx = tid & 15;

    // Load Q tile
#pragma unroll
    for (int i = 0; i < 16; i++) {
        int e = tid + i * 256;
        int r = e >> 6, d = e & 63;
        Qs[r * LDS_ + d] = qp[(qb * 64 + r) * D_ + d];
    }
    if (tid < 64) { mrow[tid] = -1e30f; lrow[tid] = 0.f; }

    float acc[4][4];
#pragma unroll
    for (int i = 0; i < 4; i++)
#pragma unroll
        for (int j = 0; j < 4; j++) acc[i][j] = 0.f;

    __syncthreads();

    for (int kb = 0; kb <= qb; kb++) {
        // Load K tile
#pragma unroll
        for (int i = 0; i < 16; i++) {
            int e = tid + i * 256;
            int r = e >> 6, d = e & 63;
            KVs[r * LDS_ + d] = kp[(kb * 64 + r) * D_ + d];
        }
        __syncthreads();

        // S = Q @ K^T
        float s[4][4];
#pragma unroll
        for (int i = 0; i < 4; i++)
#pragma unroll
            for (int j = 0; j < 4; j++) s[i][j] = 0.f;
#pragma unroll
        for (int d = 0; d < 64; d++) {
            float a[4], bq[4];
#pragma unroll
            for (int i = 0; i < 4; i++) a[i]  = Qs[(ty * 4 + i) * LDS_ + d];
#pragma unroll
            for (int j = 0; j < 4; j++) bq[j] = KVs[(tx * 4 + j) * LDS_ + d];
#pragma unroll
            for (int i = 0; i < 4; i++)
#pragma unroll
                for (int j = 0; j < 4; j++) s[i][j] += a[i] * bq[j];
        }
        const bool diag = (kb == qb);
#pragma unroll
        for (int i = 0; i < 4; i++) {
            int r = ty * 4 + i;
#pragma unroll
            for (int j = 0; j < 4; j++) {
                int c = tx * 4 + j;
                float v = s[i][j] * 0.125f;   // 1/sqrt(64)
                if (diag && c > r) v = -1e30f;
                Ss[r * LDS_ + c] = v;
            }
        }
        __syncthreads();

        // Online softmax (one thread per row)
        if (tid < 64) {
            int r = tid;
            float mold = mrow[r];
            float mx = mold;
#pragma unroll 8
            for (int s2 = 0; s2 < 64; s2++) mx = fmaxf(mx, Ss[r * LDS_ + s2]);
            float corr = __expf(mold - mx);
            float sum = 0.f;
#pragma unroll 8
            for (int s2 = 0; s2 < 64; s2++) {
                float p = __expf(Ss[r * LDS_ + s2] - mx);
                Ss[r * LDS_ + s2] = p;
                sum += p;
            }
            lrow[r] = lrow[r] * corr + sum;
            mrow[r] = mx;
            crow[r] = corr;
        }
        __syncthreads();

        // Rescale running acc; load V tile (reuses KVs)
#pragma unroll
        for (int i = 0; i < 4; i++) {
            float cr = crow[ty * 4 + i];
#pragma unroll
            for (int j = 0; j < 4; j++) acc[i][j] *= cr;
        }
#pragma unroll
        for (int i = 0; i < 16; i++) {
            int e = tid + i * 256;
            int r = e >> 6, d = e & 63;
            KVs[r * LDS_ + d] = vp[(kb * 64 + r) * D_ + d];
        }
        __syncthreads();

        // acc += P @ V
#pragma unroll
        for (int s2 = 0; s2 < 64; s2++) {
            float a[4], bv[4];
#pragma unroll
            for (int i = 0; i < 4; i++) a[i]  = Ss[(ty * 4 + i) * LDS_ + s2];
#pragma unroll
            for (int j = 0; j < 4; j++) bv[j] = KVs[s2 * LDS_ + tx * 4 + j];
#pragma unroll
            for (int i = 0; i < 4; i++)
#pragma unroll
                for (int j = 0; j < 4; j++) acc[i][j] += a[i] * bv[j];
        }
        __syncthreads();
    }

    // Write O = acc / l
#pragma unroll
    for (int i = 0; i < 4; i++) {
        int r = ty * 4 + i;
        float inv = 1.f / lrow[r];
        float* op = &g_o[(size_t)((b * H_ + h) * T_ + qb * 64 + r) * D_ + tx * 4];
#pragma unroll
        for (int j = 0; j < 4; j++) op[j] = acc[i][j] * inv;
    }
}

// ---------------------------------------------------------------------------
// Kernel 3: output projection. out[16384,384] = Ctx[16384,384] @ Wp + bp,
// where Ctx gathers from g_o ([B,H,T,D] -> [B,T,H*D]).
// ---------------------------------------------------------------------------
__global__ __launch_bounds__(256) void proj_kernel(const float* __restrict__ Wp,
                                                   const float* __restrict__ bp,
                                                   float* __restrict__ out) {
    const int m0 = blockIdx.x * 64;
    const int n0 = blockIdx.y * 64;

    __shared__ float As[16][64];   // [k][m]
    __shared__ float Bs[16][68];   // [k][n]

    const int tid = threadIdx.x;
    const int ty = tid >> 4, tx = tid & 15;

    float acc[4][4];
#pragma unroll
    for (int i = 0; i < 4; i++)
#pragma unroll
        for (int j = 0; j < 4; j++) acc[i][j] = 0.f;

    for (int k0 = 0; k0 < C_; k0 += 16) {
        const int hh = k0 >> 6;          // head for this k-chunk (16 | 64)
        const int dbase = k0 & 63;
#pragma unroll
        for (int i = 0; i < 4; i++) {
            int e = tid + i * 256;
            int r = e >> 4, c = e & 15;
            int m = m0 + r;
            int bb = m >> 8, t = m & 255;
            As[c][r] = g_o[(size_t)((bb * H_ + hh) * T_ + t) * D_ + dbase + c];
        }
#pragma unroll
        for (int i = 0; i < 4; i++) {
            int e = tid + i * 256;
            int r = e >> 6, c = e & 63;
            Bs[r][c] = Wp[(k0 + r) * C_ + n0 + c];
        }
        __syncthreads();
#pragma unroll
        for (int k = 0; k < 16; k++) {
            float a[4], b[4];
#pragma unroll
            for (int i = 0; i < 4; i++) a[i] = As[k][ty * 4 + i];
#pragma unroll
            for (int j = 0; j < 4; j++) b[j] = Bs[k][tx * 4 + j];
#pragma unroll
            for (int i = 0; i < 4; i++)
#pragma unroll
                for (int j = 0; j < 4; j++) acc[i][j] += a[i] * b[j];
        }
        __syncthreads();
    }

#pragma unroll
    for (int i = 0; i < 4; i++) {
        int m = m0 + ty * 4 + i;
        float* op = &out[(size_t)m * C_ + n0 + tx * 4];
#pragma unroll
        for (int j = 0; j < 4; j++) op[j] = acc[i][j] + bp[n0 + tx * 4 + j];
    }
}

// ---------------------------------------------------------------------------
extern "C" void kernel_launch(void* const* d_in, const int* in_sizes, int n_in,
                              void* d_out, int out_size) {
    const float* x  = (const float*)d_in[0];
    const float* Wq = (const float*)d_in[1];
    const float* Wk = (const float*)d_in[2];
    const float* Wv = (const float*)d_in[3];
    const float* Wp = (const float*)d_in[4];
    const float* bp = (const float*)d_in[5];
    float* out = (float*)d_out;

    cudaFuncSetAttribute(attn_kernel, cudaFuncAttributeMaxDynamicSharedMemorySize,
                         ATTN_SMEM_BYTES);

    qkv_kernel<<<dim3(M_ / 64, 3 * H_), 256>>>(x, Wq, Wk, Wv);
    attn_kernel<<<dim3(T_ / 64, H_, B_), 256, ATTN_SMEM_BYTES>>>();
    proj_kernel<<<dim3(M_ / 64, C_ / 64), 256>>>(Wp, bp, out);
}

// round 2
// speedup vs baseline: 1.7981x; 1.7981x over previous
#include <cuda_runtime.h>
#include <mma.h>
using namespace nvcuda;

#define B_ 64
#define T_ 256
#define C_ 384
#define H_ 6
#define D_ 64
#define M_ (B_*T_)

// Scratch (allocation-free rule: __device__ globals)
__device__ float g_q[B_*H_*T_*D_];
__device__ float g_k[B_*H_*T_*D_];
__device__ float g_v[B_*H_*T_*D_];
__device__ float g_o[B_*H_*T_*D_];

typedef wmma::fragment<wmma::matrix_a, 16, 16, 8, wmma::precision::tf32, wmma::row_major> FragA;
typedef wmma::fragment<wmma::matrix_b, 16, 16, 8, wmma::precision::tf32, wmma::row_major> FragB;
typedef wmma::fragment<wmma::matrix_b, 16, 16, 8, wmma::precision::tf32, wmma::col_major> FragBT;
typedef wmma::fragment<wmma::accumulator, 16, 16, 8, float> FragC;

template <class Frag>
__device__ __forceinline__ void cvt_tf32(Frag& f) {
#pragma unroll
    for (int i = 0; i < f.num_elements; i++) f.x[i] = wmma::__float_to_tf32(f.x[i]);
}

// ---------------------------------------------------------------------------
// Kernel 1: fused QKV projection.  Y[16384, 3*384] = X[16384,384] @ Wcat.
// CTA tile 128x128, 8 warps (4 row groups x 2 col groups), warp = 32x64.
// Column n -> (mat, head, d); output scattered to g_q/g_k/g_v in [B,H,T,D].
// ---------------------------------------------------------------------------
__global__ __launch_bounds__(256) void qkv_kernel(const float* __restrict__ x,
                                                  const float* __restrict__ Wq,
                                                  const float* __restrict__ Wk,
                                                  const float* __restrict__ Wv) {
    __shared__ float As[128][36];    // [m][k], k-tile 32, pad to 36
    __shared__ float Bs[32][132];    // [k][n], pad to 132

    const int tid = threadIdx.x;
    const int wid = tid >> 5;
    const int wr = wid & 3;          // row group (0..3) -> 32 rows
    const int wc = wid >> 2;         // col group (0..1) -> 64 cols
    const int m0 = blockIdx.x * 128;
    const int by = blockIdx.y;       // 0..8
    const int mat = by / 3;
    const int nb = (by % 3) * 128;   // col offset within this mat (0..383)
    const float* W = (mat == 0 ? Wq : (mat == 1 ? Wk : Wv));
    float* outp    = (mat == 0 ? g_q : (mat == 1 ? g_k : g_v));

    FragC acc[2][4];
#pragma unroll
    for (int i = 0; i < 2; i++)
#pragma unroll
        for (int j = 0; j < 4; j++) wmma::fill_fragment(acc[i][j], 0.0f);

    for (int k0 = 0; k0 < C_; k0 += 32) {
        // A: 128x32 floats = 1024 float4
#pragma unroll
        for (int i = 0; i < 4; i++) {
            int idx = tid + i * 256;
            int r = idx >> 3, c4 = idx & 7;
            *(float4*)&As[r][c4 * 4] =
                *(const float4*)&x[(size_t)(m0 + r) * C_ + k0 + c4 * 4];
        }
        // B: 32x128 floats = 1024 float4, gathered from W[h][k][d]
#pragma unroll
        for (int i = 0; i < 4; i++) {
            int idx = tid + i * 256;
            int k = idx >> 5, n4 = idx & 31;
            int nm = nb + n4 * 4;
            int h = nm >> 6, d = nm & 63;
            *(float4*)&Bs[k][n4 * 4] =
                *(const float4*)&W[(size_t)h * C_ * D_ + (k0 + k) * D_ + d];
        }
        __syncthreads();
#pragma unroll
        for (int kk = 0; kk < 4; kk++) {
            FragA a[2];
            FragB b[4];
#pragma unroll
            for (int i = 0; i < 2; i++) {
                wmma::load_matrix_sync(a[i], &As[wr * 32 + i * 16][kk * 8], 36);
                cvt_tf32(a[i]);
            }
#pragma unroll
            for (int j = 0; j < 4; j++) {
                wmma::load_matrix_sync(b[j], &Bs[kk * 8][wc * 64 + j * 16], 132);
                cvt_tf32(b[j]);
            }
#pragma unroll
            for (int i = 0; i < 2; i++)
#pragma unroll
                for (int j = 0; j < 4; j++)
                    wmma::mma_sync(acc[i][j], a[i], b[j], acc[i][j]);
        }
        __syncthreads();
    }

    const int b = m0 >> 8;          // tile lies fully in one batch (128 | 256)
    const int t0 = m0 & 255;
#pragma unroll
    for (int i = 0; i < 2; i++) {
#pragma unroll
        for (int j = 0; j < 4; j++) {
            int nm = nb + wc * 64 + j * 16;
            int h = nm >> 6, d0 = nm & 63;
            float* op = outp + (size_t)((b * H_ + h) * T_ + t0 + wr * 32 + i * 16) * D_ + d0;
            wmma::store_matrix_sync(op, acc[i][j], D_, wmma::mem_row_major);
        }
    }
}

// ---------------------------------------------------------------------------
// Kernel 2: causal attention, full-row-panel variant (T=256 fits in smem).
// One CTA per (b, h, 64-row q tile), 128 threads = 4 warps, 16 q-rows/warp.
// S panel 64 x L (L=(qb+1)*64) in smem -> single softmax pass, no rescaling.
// ---------------------------------------------------------------------------
#define LDQ_ 68
#define LDS_ 264
#define ATTN_SMEM_FLOATS (64 * LDQ_ + 64 * LDQ_ + 64 * LDS_)
#define ATTN_SMEM_BYTES  (ATTN_SMEM_FLOATS * 4)

__global__ __launch_bounds__(128) void attn_kernel() {
    extern __shared__ float sm[];
    float* Qs  = sm;                    // 64 x LDQ_
    float* KVs = sm + 64 * LDQ_;        // 64 x LDQ_ (K then V)
    float* Ss  = sm + 2 * 64 * LDQ_;    // 64 x LDS_

    const int qb = blockIdx.x;          // 0..3
    const int h  = blockIdx.y;
    const int b  = blockIdx.z;
    const size_t base = (size_t)((b * H_ + h) * T_) * D_;
    const float* qp = g_q + base + (size_t)qb * 64 * D_;
    const float* kp = g_k + base;
    const float* vp = g_v + base;

    const int tid = threadIdx.x;
    const int lane = tid & 31;
    const int wid = tid >> 5;
    const int L = (qb + 1) * 64;

    // Load Q tile (64x64)
#pragma unroll
    for (int i = 0; i < 8; i++) {
        int idx = tid + i * 128;
        int r = idx >> 4, c4 = idx & 15;
        *(float4*)&Qs[r * LDQ_ + c4 * 4] = *(const float4*)&qp[r * D_ + c4 * 4];
    }
    __syncthreads();

    // Phase 1: S = Q @ K^T, panel by 64-wide tiles
    for (int kb = 0; kb <= qb; kb++) {
#pragma unroll
        for (int i = 0; i < 8; i++) {
            int idx = tid + i * 128;
            int r = idx >> 4, c4 = idx & 15;
            *(float4*)&KVs[r * LDQ_ + c4 * 4] =
                *(const float4*)&kp[(size_t)(kb * 64 + r) * D_ + c4 * 4];
        }
        __syncthreads();

        FragC sf[4];
#pragma unroll
        for (int j = 0; j < 4; j++) wmma::fill_fragment(sf[j], 0.0f);
#pragma unroll
        for (int kk = 0; kk < 8; kk++) {
            FragA a;
            wmma::load_matrix_sync(a, &Qs[wid * 16 * LDQ_ + kk * 8], LDQ_);
            cvt_tf32(a);
#pragma unroll
            for (int j = 0; j < 4; j++) {
                FragBT bf;   // K row-major read col-major => K^T
                wmma::load_matrix_sync(bf, &KVs[j * 16 * LDQ_ + kk * 8], LDQ_);
                cvt_tf32(bf);
                wmma::mma_sync(sf[j], a, bf, sf[j]);
            }
        }
#pragma unroll
        for (int j = 0; j < 4; j++)
            wmma::store_matrix_sync(&Ss[wid * 16 * LDS_ + kb * 64 + j * 16],
                                    sf[j], LDS_, wmma::mem_row_major);
        __syncthreads();
    }

    // Softmax (fp32, full row, causal mask), 16 rows per warp
    for (int rr = 0; rr < 16; rr++) {
        int r = wid * 16 + rr;
        int t = qb * 64 + r;
        float* Srow = &Ss[r * LDS_];
        float mx = -1e30f;
        for (int c = lane; c < L; c += 32)
            if (c <= t) mx = fmaxf(mx, Srow[c] * 0.125f);
#pragma unroll
        for (int o = 16; o; o >>= 1) mx = fmaxf(mx, __shfl_xor_sync(~0u, mx, o));
        float sum = 0.f;
        for (int c = lane; c < L; c += 32) {
            float p = (c <= t) ? __expf(Srow[c] * 0.125f - mx) : 0.f;
            Srow[c] = p;
            sum += p;
        }
#pragma unroll
        for (int o = 16; o; o >>= 1) sum += __shfl_xor_sync(~0u, sum, o);
        float inv = 1.f / sum;
        for (int c = lane; c < L; c += 32) Srow[c] *= inv;
    }
    __syncthreads();

    // Phase 2: O = P @ V, accumulators persist (no rescale needed)
    FragC of[4];
#pragma unroll
    for (int j = 0; j < 4; j++) wmma::fill_fragment(of[j], 0.0f);

    for (int kb = 0; kb <= qb; kb++) {
        __syncthreads();  // protect prior KVs readers before overwrite
#pragma unroll
        for (int i = 0; i < 8; i++) {
            int idx = tid + i * 128;
            int r = idx >> 4, c4 = idx & 15;
            *(float4*)&KVs[r * LDQ_ + c4 * 4] =
                *(const float4*)&vp[(size_t)(kb * 64 + r) * D_ + c4 * 4];
        }
        __syncthreads();
#pragma unroll
        for (int kk = 0; kk < 8; kk++) {
            FragA a;
            wmma::load_matrix_sync(a, &Ss[wid * 16 * LDS_ + kb * 64 + kk * 8], LDS_);
            cvt_tf32(a);
#pragma unroll
            for (int j = 0; j < 4; j++) {
                FragB bf;
                wmma::load_matrix_sync(bf, &KVs[kk * 8 * LDQ_ + j * 16], LDQ_);
                cvt_tf32(bf);
                wmma::mma_sync(of[j], a, bf, of[j]);
            }
        }
    }

    float* op = g_o + base + (size_t)(qb * 64 + wid * 16) * D_;
#pragma unroll
    for (int j = 0; j < 4; j++)
        wmma::store_matrix_sync(op + j * 16, of[j], D_, wmma::mem_row_major);
}

// ---------------------------------------------------------------------------
// Kernel 3: output projection.  out[16384,384] = Ctx @ Wp + bp.
// Ctx gathered from g_o ([B,H,T,D] -> [B,T,H*D]); bias pre-loaded into acc.
// ---------------------------------------------------------------------------
__global__ __launch_bounds__(256) void proj_kernel(const float* __restrict__ Wp,
                                                   const float* __restrict__ bp,
                                                   float* __restrict__ out) {
    __shared__ float As[128][36];
    __shared__ float Bs[32][132];
    __shared__ float bias_s[16][132];

    const int tid = threadIdx.x;
    const int wid = tid >> 5;
    const int wr = wid & 3, wc = wid >> 2;
    const int m0 = blockIdx.x * 128;
    const int n0 = blockIdx.y * 128;
    const int b = m0 >> 8;
    const int t0 = m0 & 255;

    // Stage bias replicated across 16 rows so we can load it as an acc frag
#pragma unroll
    for (int i = 0; i < 8; i++) {
        int idx = tid + i * 256;
        int r = idx >> 7, n = idx & 127;
        bias_s[r][n] = bp[n0 + n];
    }
    __syncthreads();

    FragC acc[2][4];
#pragma unroll
    for (int i = 0; i < 2; i++)
#pragma unroll
        for (int j = 0; j < 4; j++)
            wmma::load_matrix_sync(acc[i][j], &bias_s[0][wc * 64 + j * 16], 132,
                                   wmma::mem_row_major);

    for (int k0 = 0; k0 < C_; k0 += 32) {
        const int hh = k0 >> 6;
        const int d0 = k0 & 63;
        // A: gather 128x32 from g_o
#pragma unroll
        for (int i = 0; i < 4; i++) {
            int idx = tid + i * 256;
            int r = idx >> 3, c4 = idx & 7;
            *(float4*)&As[r][c4 * 4] =
                *(const float4*)&g_o[(size_t)((b * H_ + hh) * T_ + t0 + r) * D_ + d0 + c4 * 4];
        }
        // B: 32x128 from Wp
#pragma unroll
        for (int i = 0; i < 4; i++) {
            int idx = tid + i * 256;
            int k = idx >> 5, n4 = idx & 31;
            *(float4*)&Bs[k][n4 * 4] =
                *(const float4*)&Wp[(size_t)(k0 + k) * C_ + n0 + n4 * 4];
        }
        __syncthreads();
#pragma unroll
        for (int kk = 0; kk < 4; kk++) {
            FragA a[2];
            FragB bfr[4];
#pragma unroll
            for (int i = 0; i < 2; i++) {
                wmma::load_matrix_sync(a[i], &As[wr * 32 + i * 16][kk * 8], 36);
                cvt_tf32(a[i]);
            }
#pragma unroll
            for (int j = 0; j < 4; j++) {
                wmma::load_matrix_sync(bfr[j], &Bs[kk * 8][wc * 64 + j * 16], 132);
                cvt_tf32(bfr[j]);
            }
#pragma unroll
            for (int i = 0; i < 2; i++)
#pragma unroll
                for (int j = 0; j < 4; j++)
                    wmma::mma_sync(acc[i][j], a[i], bfr[j], acc[i][j]);
        }
        __syncthreads();
    }

#pragma unroll
    for (int i = 0; i < 2; i++)
#pragma unroll
        for (int j = 0; j < 4; j++) {
            float* op = out + (size_t)(m0 + wr * 32 + i * 16) * C_ + n0 + wc * 64 + j * 16;
            wmma::store_matrix_sync(op, acc[i][j], C_, wmma::mem_row_major);
        }
}

// ---------------------------------------------------------------------------
extern "C" void kernel_launch(void* const* d_in, const int* in_sizes, int n_in,
                              void* d_out, int out_size) {
    const float* x  = (const float*)d_in[0];
    const float* Wq = (const float*)d_in[1];
    const float* Wk = (const float*)d_in[2];
    const float* Wv = (const float*)d_in[3];
    const float* Wp = (const float*)d_in[4];
    const float* bp = (const float*)d_in[5];
    float* out = (float*)d_out;

    cudaFuncSetAttribute(attn_kernel, cudaFuncAttributeMaxDynamicSharedMemorySize,
                         ATTN_SMEM_BYTES);

    qkv_kernel<<<dim3(M_ / 128, 9), 256>>>(x, Wq, Wk, Wv);
    attn_kernel<<<dim3(T_ / 64, H_, B_), 128, ATTN_SMEM_BYTES>>>();
    proj_kernel<<<dim3(M_ / 128, C_ / 128), 256>>>(Wp, bp, out);
}

// round 4
// speedup vs baseline: 2.0046x; 1.1149x over previous
#include <cuda_runtime.h>
#include <mma.h>
using namespace nvcuda;

#define B_ 64
#define T_ 256
#define C_ 384
#define H_ 6
#define D_ 64
#define M_ (B_*T_)

// Scratch (allocation-free rule: __device__ globals)
__device__ float g_q[B_*H_*T_*D_];
__device__ float g_k[B_*H_*T_*D_];
__device__ float g_v[B_*H_*T_*D_];
__device__ float g_o[B_*H_*T_*D_];

typedef wmma::fragment<wmma::matrix_a, 16, 16, 8, wmma::precision::tf32, wmma::row_major> FragA;
typedef wmma::fragment<wmma::matrix_b, 16, 16, 8, wmma::precision::tf32, wmma::row_major> FragB;
typedef wmma::fragment<wmma::matrix_b, 16, 16, 8, wmma::precision::tf32, wmma::col_major> FragBT;
typedef wmma::fragment<wmma::accumulator, 16, 16, 8, float> FragC;

__device__ __forceinline__ float tf32r(float x) { return wmma::__float_to_tf32(x); }
__device__ __forceinline__ float4 tf32r4(float4 v) {
    v.x = tf32r(v.x); v.y = tf32r(v.y); v.z = tf32r(v.z); v.w = tf32r(v.w);
    return v;
}

// ---------------------------------------------------------------------------
// Kernel 1: fused QKV projection. CTA = 128 threads, tile 128(M) x 64(N),
// double-buffered smem, tf32 rounding at staging. grid = (128, 18).
// ---------------------------------------------------------------------------
#define QKV_A_ELEMS (128*36)
#define QKV_B_ELEMS (32*68)
#define QKV_SMEM_BYTES ((2*(QKV_A_ELEMS + QKV_B_ELEMS))*4)

__global__ __launch_bounds__(128) void qkv_kernel(const float* __restrict__ x,
                                                  const float* __restrict__ Wq,
                                                  const float* __restrict__ Wk,
                                                  const float* __restrict__ Wv) {
    extern __shared__ float sm[];
    float* As = sm;                        // [2][128][36]
    float* Bs = sm + 2 * QKV_A_ELEMS;      // [2][32][68]

    const int tid = threadIdx.x;
    const int wid = tid >> 5;
    const int m0 = blockIdx.x * 128;
    const int by = blockIdx.y;             // 0..17
    const int mat = by / H_;
    const int h   = by % H_;
    const float* W = (mat == 0 ? Wq : (mat == 1 ? Wk : Wv)) + (size_t)h * C_ * D_;
    float* outp    = (mat == 0 ? g_q : (mat == 1 ? g_k : g_v));

    FragC acc[2][4];
#pragma unroll
    for (int i = 0; i < 2; i++)
#pragma unroll
        for (int j = 0; j < 4; j++) wmma::fill_fragment(acc[i][j], 0.0f);

    // stage tile (k0) into buffer buf
    auto stage = [&](int k0, int buf) {
        float* Ab = As + buf * QKV_A_ELEMS;
        float* Bb = Bs + buf * QKV_B_ELEMS;
#pragma unroll
        for (int i = 0; i < 8; i++) {
            int idx = tid + i * 128;
            int r = idx >> 3, c4 = idx & 7;
            float4 v = *(const float4*)&x[(size_t)(m0 + r) * C_ + k0 + c4 * 4];
            *(float4*)&Ab[r * 36 + c4 * 4] = tf32r4(v);
        }
#pragma unroll
        for (int i = 0; i < 4; i++) {
            int idx = tid + i * 128;
            int k = idx >> 4, n4 = idx & 15;
            float4 v = *(const float4*)&W[(size_t)(k0 + k) * D_ + n4 * 4];
            *(float4*)&Bb[k * 68 + n4 * 4] = tf32r4(v);
        }
    };

    stage(0, 0);
    __syncthreads();

    for (int kt = 0; kt < 12; kt++) {
        const int cur = kt & 1;
        if (kt < 11) stage((kt + 1) * 32, cur ^ 1);
        const float* Ab = As + cur * QKV_A_ELEMS;
        const float* Bb = Bs + cur * QKV_B_ELEMS;
#pragma unroll
        for (int kk = 0; kk < 4; kk++) {
            FragA a[2];
            FragB b[4];
#pragma unroll
            for (int i = 0; i < 2; i++)
                wmma::load_matrix_sync(a[i], &Ab[(wid * 32 + i * 16) * 36 + kk * 8], 36);
#pragma unroll
            for (int j = 0; j < 4; j++)
                wmma::load_matrix_sync(b[j], &Bb[(kk * 8) * 68 + j * 16], 68);
#pragma unroll
            for (int i = 0; i < 2; i++)
#pragma unroll
                for (int j = 0; j < 4; j++)
                    wmma::mma_sync(acc[i][j], a[i], b[j], acc[i][j]);
        }
        __syncthreads();
    }

    const int b = m0 >> 8, t0 = m0 & 255;
#pragma unroll
    for (int i = 0; i < 2; i++)
#pragma unroll
        for (int j = 0; j < 4; j++) {
            float* op = outp + (size_t)((b * H_ + h) * T_ + t0 + wid * 32 + i * 16) * D_ + j * 16;
            wmma::store_matrix_sync(op, acc[i][j], D_, wmma::mem_row_major);
        }
}

// ---------------------------------------------------------------------------
// Kernel 2: causal attention. CTA = 256 threads (8 warps), 128-row q tile.
// Full S row-panel in smem -> one-shot softmax. grid = (2, 6, 64).
// ---------------------------------------------------------------------------
#define LDQ_ 68
#define LDS_ 264
#define ATTN_SMEM_BYTES ((128*LDQ_ + 64*LDQ_ + 128*LDS_)*4)

__global__ __launch_bounds__(256) void attn_kernel() {
    extern __shared__ float sm[];
    float* Qs  = sm;                           // 128 x LDQ_ (pre-scaled by 0.125)
    float* KVs = sm + 128 * LDQ_;              // 64 x LDQ_ (K then V)
    float* Ss  = sm + 128 * LDQ_ + 64 * LDQ_;  // 128 x LDS_

    const int qt = blockIdx.x;                 // 0..1 (128-row tiles)
    const int h  = blockIdx.y;
    const int b  = blockIdx.z;
    const size_t base = (size_t)((b * H_ + h) * T_) * D_;
    const float* qp = g_q + base + (size_t)qt * 128 * D_;
    const float* kp = g_k + base;
    const float* vp = g_v + base;

    const int tid = threadIdx.x;
    const int lane = tid & 31;
    const int wid = tid >> 5;
    const int kbmax = 2 * qt + 1;
    const int L = (kbmax + 1) * 64;

    // Load Q tile (128x64), pre-scaled + tf32-rounded
#pragma unroll
    for (int i = 0; i < 8; i++) {
        int idx = tid + i * 256;
        int r = idx >> 4, c4 = idx & 15;
        float4 v = *(const float4*)&qp[(size_t)r * D_ + c4 * 4];
        v.x *= 0.125f; v.y *= 0.125f; v.z *= 0.125f; v.w *= 0.125f;
        *(float4*)&Qs[r * LDQ_ + c4 * 4] = tf32r4(v);
    }
    __syncthreads();

    // Phase 1: S = (Q*scale) @ K^T
    for (int kb = 0; kb <= kbmax; kb++) {
#pragma unroll
        for (int i = 0; i < 4; i++) {
            int idx = tid + i * 256;
            int r = idx >> 4, c4 = idx & 15;
            float4 v = *(const float4*)&kp[(size_t)(kb * 64 + r) * D_ + c4 * 4];
            *(float4*)&KVs[r * LDQ_ + c4 * 4] = tf32r4(v);
        }
        __syncthreads();

        FragC sf[4];
#pragma unroll
        for (int j = 0; j < 4; j++) wmma::fill_fragment(sf[j], 0.0f);
#pragma unroll
        for (int kk = 0; kk < 8; kk++) {
            FragA a;
            wmma::load_matrix_sync(a, &Qs[(wid * 16) * LDQ_ + kk * 8], LDQ_);
#pragma unroll
            for (int j = 0; j < 4; j++) {
                FragBT bt;   // K row-major read col-major => K^T
                wmma::load_matrix_sync(bt, &KVs[(j * 16) * LDQ_ + kk * 8], LDQ_);
                wmma::mma_sync(sf[j], a, bt, sf[j]);
            }
        }
#pragma unroll
        for (int j = 0; j < 4; j++)
            wmma::store_matrix_sync(&Ss[(wid * 16) * LDS_ + kb * 64 + j * 16],
                                    sf[j], LDS_, wmma::mem_row_major);
        __syncthreads();
    }

    // Softmax (fp32, full row, causal), 16 rows per warp; write P as tf32
    for (int rr = 0; rr < 16; rr++) {
        int r = wid * 16 + rr;
        int t = qt * 128 + r;
        float* Srow = &Ss[r * LDS_];
        float mx = -1e30f;
        for (int c = lane; c < L; c += 32)
            if (c <= t) mx = fmaxf(mx, Srow[c]);
#pragma unroll
        for (int o = 16; o; o >>= 1) mx = fmaxf(mx, __shfl_xor_sync(~0u, mx, o));
        float sum = 0.f;
        for (int c = lane; c < L; c += 32) {
            float p = (c <= t) ? __expf(Srow[c] - mx) : 0.f;
            Srow[c] = p;
            sum += p;
        }
#pragma unroll
        for (int o = 16; o; o >>= 1) sum += __shfl_xor_sync(~0u, sum, o);
        float inv = 1.f / sum;
        for (int c = lane; c < L; c += 32) Srow[c] = tf32r(Srow[c] * inv);
    }

    // Phase 2: O = P @ V
    FragC of[4];
#pragma unroll
    for (int j = 0; j < 4; j++) wmma::fill_fragment(of[j], 0.0f);

    for (int kb = 0; kb <= kbmax; kb++) {
        __syncthreads();   // all warps done reading KVs (and, first iter, Ss writes visible)
#pragma unroll
        for (int i = 0; i < 4; i++) {
            int idx = tid + i * 256;
            int r = idx >> 4, c4 = idx & 15;
            float4 v = *(const float4*)&vp[(size_t)(kb * 64 + r) * D_ + c4 * 4];
            *(float4*)&KVs[r * LDQ_ + c4 * 4] = tf32r4(v);
        }
        __syncthreads();
#pragma unroll
        for (int kk = 0; kk < 8; kk++) {
            FragA a;
            wmma::load_matrix_sync(a, &Ss[(wid * 16) * LDS_ + kb * 64 + kk * 8], LDS_);
#pragma unroll
            for (int j = 0; j < 4; j++) {
                FragB bf;
                wmma::load_matrix_sync(bf, &KVs[(kk * 8) * LDQ_ + j * 16], LDQ_);
                wmma::mma_sync(of[j], a, bf, of[j]);
            }
        }
    }

    float* op = g_o + base + (size_t)(qt * 128 + wid * 16) * D_;
#pragma unroll
    for (int j = 0; j < 4; j++)
        wmma::store_matrix_sync(op + j * 16, of[j], D_, wmma::mem_row_major);
}

// ---------------------------------------------------------------------------
// Kernel 3: output projection. CTA = 128 threads, tile 128 x 64,
// double-buffered, bias pre-loaded into accumulators. grid = (128, 6).
// ---------------------------------------------------------------------------
#define PROJ_SMEM_BYTES ((2*(QKV_A_ELEMS + QKV_B_ELEMS) + 16*68)*4)

__global__ __launch_bounds__(128) void proj_kernel(const float* __restrict__ Wp,
                                                   const float* __restrict__ bp,
                                                   float* __restrict__ out) {
    extern __shared__ float sm[];
    float* As = sm;                                      // [2][128][36]
    float* Bs = sm + 2 * QKV_A_ELEMS;                    // [2][32][68]
    float* bias_s = sm + 2 * (QKV_A_ELEMS + QKV_B_ELEMS); // [16][68]

    const int tid = threadIdx.x;
    const int wid = tid >> 5;
    const int m0 = blockIdx.x * 128;
    const int n0 = blockIdx.y * 64;
    const int b = m0 >> 8, t0 = m0 & 255;

    // Stage bias replicated across 16 rows
#pragma unroll
    for (int i = 0; i < 2; i++) {
        int idx = tid + i * 128;
        int r = idx >> 4, c4 = idx & 15;
        *(float4*)&bias_s[r * 68 + c4 * 4] = *(const float4*)&bp[n0 + c4 * 4];
    }
    __syncthreads();

    FragC acc[2][4];
#pragma unroll
    for (int i = 0; i < 2; i++)
#pragma unroll
        for (int j = 0; j < 4; j++)
            wmma::load_matrix_sync(acc[i][j], &bias_s[j * 16], 68, wmma::mem_row_major);

    auto stage = [&](int k0, int buf) {
        float* Ab = As + buf * QKV_A_ELEMS;
        float* Bb = Bs + buf * QKV_B_ELEMS;
        const int hh = k0 >> 6, d0 = k0 & 63;
#pragma unroll
        for (int i = 0; i < 8; i++) {
            int idx = tid + i * 128;
            int r = idx >> 3, c4 = idx & 7;
            float4 v = *(const float4*)&g_o[(size_t)((b * H_ + hh) * T_ + t0 + r) * D_ + d0 + c4 * 4];
            *(float4*)&Ab[r * 36 + c4 * 4] = tf32r4(v);
        }
#pragma unroll
        for (int i = 0; i < 4; i++) {
            int idx = tid + i * 128;
            int k = idx >> 4, n4 = idx & 15;
            float4 v = *(const float4*)&Wp[(size_t)(k0 + k) * C_ + n0 + n4 * 4];
            *(float4*)&Bb[k * 68 + n4 * 4] = tf32r4(v);
        }
    };

    stage(0, 0);
    __syncthreads();

    for (int kt = 0; kt < 12; kt++) {
        const int cur = kt & 1;
        if (kt < 11) stage((kt + 1) * 32, cur ^ 1);
        const float* Ab = As + cur * QKV_A_ELEMS;
        const float* Bb = Bs + cur * QKV_B_ELEMS;
#pragma unroll
        for (int kk = 0; kk < 4; kk++) {
            FragA a[2];
            FragB bf[4];
#pragma unroll
            for (int i = 0; i < 2; i++)
                wmma::load_matrix_sync(a[i], &Ab[(wid * 32 + i * 16) * 36 + kk * 8], 36);
#pragma unroll
            for (int j = 0; j < 4; j++)
                wmma::load_matrix_sync(bf[j], &Bb[(kk * 8) * 68 + j * 16], 68);
#pragma unroll
            for (int i = 0; i < 2; i++)
#pragma unroll
                for (int j = 0; j < 4; j++)
                    wmma::mma_sync(acc[i][j], a[i], bf[j], acc[i][j]);
        }
        __syncthreads();
    }

#pragma unroll
    for (int i = 0; i < 2; i++)
#pragma unroll
        for (int j = 0; j < 4; j++) {
            float* op = out + (size_t)(m0 + wid * 32 + i * 16) * C_ + n0 + j * 16;
            wmma::store_matrix_sync(op, acc[i][j], C_, wmma::mem_row_major);
        }
}

// ---------------------------------------------------------------------------
extern "C" void kernel_launch(void* const* d_in, const int* in_sizes, int n_in,
                              void* d_out, int out_size) {
    const float* x  = (const float*)d_in[0];
    const float* Wq = (const float*)d_in[1];
    const float* Wk = (const float*)d_in[2];
    const float* Wv = (const float*)d_in[3];
    const float* Wp = (const float*)d_in[4];
    const float* bp = (const float*)d_in[5];
    float* out = (float*)d_out;

    cudaFuncSetAttribute(qkv_kernel, cudaFuncAttributeMaxDynamicSharedMemorySize,
                         QKV_SMEM_BYTES);
    cudaFuncSetAttribute(attn_kernel, cudaFuncAttributeMaxDynamicSharedMemorySize,
                         ATTN_SMEM_BYTES);
    cudaFuncSetAttribute(proj_kernel, cudaFuncAttributeMaxDynamicSharedMemorySize,
                         PROJ_SMEM_BYTES);

    qkv_kernel<<<dim3(M_ / 128, 3 * H_), 128, QKV_SMEM_BYTES>>>(x, Wq, Wk, Wv);
    attn_kernel<<<dim3(T_ / 128, H_, B_), 256, ATTN_SMEM_BYTES>>>();
    proj_kernel<<<dim3(M_ / 128, C_ / 64), 128, PROJ_SMEM_BYTES>>>(Wp, bp, out);
}

// round 5
// speedup vs baseline: 4.0263x; 2.0085x over previous
#include <cuda_runtime.h>
#include <cuda_fp16.h>
#include <mma.h>
using namespace nvcuda;

#define B_ 64
#define T_ 256
#define C_ 384
#define H_ 6
#define D_ 64
#define M_ (B_*T_)

// Scratch (allocation-free rule: __device__ globals) — fp32
__device__ float g_q[B_*H_*T_*D_];
__device__ float g_k[B_*H_*T_*D_];
__device__ float g_v[B_*H_*T_*D_];
__device__ float g_o[B_*H_*T_*D_];

typedef wmma::fragment<wmma::matrix_a, 16, 16, 16, __half, wmma::row_major> HFragA;
typedef wmma::fragment<wmma::matrix_b, 16, 16, 16, __half, wmma::row_major> HFragB;
typedef wmma::fragment<wmma::matrix_b, 16, 16, 16, __half, wmma::col_major> HFragBT;
typedef wmma::fragment<wmma::accumulator, 16, 16, 16, float> HFragC;

// convert float4 -> 4 halves, single 8-byte store (dst 8B-aligned)
__device__ __forceinline__ void sth4(__half* dst, float4 v) {
    union { __half2 h[2]; uint2 u; } t;
    t.h[0] = __floats2half2_rn(v.x, v.y);
    t.h[1] = __floats2half2_rn(v.z, v.w);
    *(uint2*)dst = t.u;
}

// ---------------------------------------------------------------------------
// Kernel 1: fused QKV projection. 128 thr (4 warps), tile 128(M) x 64(N),
// K-tile 64, double-buffered fp16 smem. grid = (128, 18).
// ---------------------------------------------------------------------------
#define QA_H (128*72)
#define QB_H (64*72)
#define QKV_SMEM_BYTES ((2*(QA_H + QB_H))*2)

__global__ __launch_bounds__(128) void qkv_kernel(const float* __restrict__ x,
                                                  const float* __restrict__ Wq,
                                                  const float* __restrict__ Wk,
                                                  const float* __restrict__ Wv) {
    extern __shared__ __half smh[];
    __half* Ah = smh;               // [2][128][72]
    __half* Bh = smh + 2 * QA_H;    // [2][64][72]

    const int tid = threadIdx.x;
    const int wid = tid >> 5;
    const int m0 = blockIdx.x * 128;
    const int by = blockIdx.y;      // 0..17
    const int mat = by / H_;
    const int h   = by % H_;
    const float* W = (mat == 0 ? Wq : (mat == 1 ? Wk : Wv)) + (size_t)h * C_ * D_;
    float* outp    = (mat == 0 ? g_q : (mat == 1 ? g_k : g_v));

    HFragC acc[2][4];
#pragma unroll
    for (int i = 0; i < 2; i++)
#pragma unroll
        for (int j = 0; j < 4; j++) wmma::fill_fragment(acc[i][j], 0.0f);

    auto stage = [&](int k0, int buf) {
        __half* Ab = Ah + buf * QA_H;
        __half* Bb = Bh + buf * QB_H;
#pragma unroll
        for (int i = 0; i < 16; i++) {           // A: 128x64
            int idx = tid + i * 128;
            int r = idx >> 4, c4 = idx & 15;
            float4 v = *(const float4*)&x[(size_t)(m0 + r) * C_ + k0 + c4 * 4];
            sth4(&Ab[r * 72 + c4 * 4], v);
        }
#pragma unroll
        for (int i = 0; i < 8; i++) {            // B: 64x64
            int idx = tid + i * 128;
            int k = idx >> 4, c4 = idx & 15;
            float4 v = *(const float4*)&W[(size_t)(k0 + k) * D_ + c4 * 4];
            sth4(&Bb[k * 72 + c4 * 4], v);
        }
    };

    stage(0, 0);
    __syncthreads();

    for (int kt = 0; kt < 6; kt++) {
        const int cur = kt & 1;
        if (kt < 5) stage((kt + 1) * 64, cur ^ 1);
        const __half* Ab = Ah + cur * QA_H;
        const __half* Bb = Bh + cur * QB_H;
#pragma unroll
        for (int kk = 0; kk < 4; kk++) {
            HFragA a[2];
            HFragB b[4];
#pragma unroll
            for (int i = 0; i < 2; i++)
                wmma::load_matrix_sync(a[i], &Ab[(wid * 32 + i * 16) * 72 + kk * 16], 72);
#pragma unroll
            for (int j = 0; j < 4; j++)
                wmma::load_matrix_sync(b[j], &Bb[(kk * 16) * 72 + j * 16], 72);
#pragma unroll
            for (int i = 0; i < 2; i++)
#pragma unroll
                for (int j = 0; j < 4; j++)
                    wmma::mma_sync(acc[i][j], a[i], b[j], acc[i][j]);
        }
        __syncthreads();
    }

    const int b = m0 >> 8, t0 = m0 & 255;
#pragma unroll
    for (int i = 0; i < 2; i++)
#pragma unroll
        for (int j = 0; j < 4; j++) {
            float* op = outp + (size_t)((b * H_ + h) * T_ + t0 + wid * 32 + i * 16) * D_ + j * 16;
            wmma::store_matrix_sync(op, acc[i][j], D_, wmma::mem_row_major);
        }
}

// ---------------------------------------------------------------------------
// Kernel 2: causal attention. 256 thr (8 warps), 128-row q tile.
// fp16 tiles, fp32 S panel; softmax in regs; P converted to fp16 in-place.
// grid = (2, 6, 64).
// ---------------------------------------------------------------------------
#define LDS_ 268
#define ATTN_Q_OFF 0
#define ATTN_KV_OFF (128*72)
#define ATTN_S_OFF  ((128*72 + 64*72)*2)   // byte offset of Ss
#define ATTN_SMEM_BYTES (ATTN_S_OFF + 128*LDS_*4)

__global__ __launch_bounds__(256) void attn_kernel() {
    extern __shared__ char smc[];
    __half* Qh  = (__half*)smc;                    // 128 x 72 (pre-scaled)
    __half* KVh = (__half*)smc + ATTN_KV_OFF;      // 64 x 72 (K then V)
    float*  Ss  = (float*)(smc + ATTN_S_OFF);      // 128 x LDS_
    __half* Hs  = (__half*)Ss;                     // half view, stride 2*LDS_

    const int qt = blockIdx.x;
    const int h  = blockIdx.y;
    const int b  = blockIdx.z;
    const size_t base = (size_t)((b * H_ + h) * T_) * D_;
    const float* qp = g_q + base + (size_t)qt * 128 * D_;
    const float* kp = g_k + base;
    const float* vp = g_v + base;

    const int tid = threadIdx.x;
    const int lane = tid & 31;
    const int wid = tid >> 5;
    const int kbmax = 2 * qt + 1;
    const int L = (kbmax + 1) * 64;

    // Q tile (128x64), pre-scaled by 0.125
#pragma unroll
    for (int i = 0; i < 8; i++) {
        int idx = tid + i * 256;
        int r = idx >> 4, c4 = idx & 15;
        float4 v = *(const float4*)&qp[(size_t)r * D_ + c4 * 4];
        v.x *= 0.125f; v.y *= 0.125f; v.z *= 0.125f; v.w *= 0.125f;
        sth4(&Qh[r * 72 + c4 * 4], v);
    }
    __syncthreads();

    // Phase 1: S = (Q*scale) @ K^T
    for (int kb = 0; kb <= kbmax; kb++) {
#pragma unroll
        for (int i = 0; i < 4; i++) {
            int idx = tid + i * 256;
            int r = idx >> 4, c4 = idx & 15;
            float4 v = *(const float4*)&kp[(size_t)(kb * 64 + r) * D_ + c4 * 4];
            sth4(&KVh[r * 72 + c4 * 4], v);
        }
        __syncthreads();

        HFragC sf[4];
#pragma unroll
        for (int j = 0; j < 4; j++) wmma::fill_fragment(sf[j], 0.0f);
#pragma unroll
        for (int kk = 0; kk < 4; kk++) {
            HFragA a;
            wmma::load_matrix_sync(a, &Qh[(wid * 16) * 72 + kk * 16], 72);
#pragma unroll
            for (int j = 0; j < 4; j++) {
                HFragBT bt;   // K row-major read col-major => K^T
                wmma::load_matrix_sync(bt, &KVh[(j * 16) * 72 + kk * 16], 72);
                wmma::mma_sync(sf[j], a, bt, sf[j]);
            }
        }
#pragma unroll
        for (int j = 0; j < 4; j++)
            wmma::store_matrix_sync(&Ss[(wid * 16) * LDS_ + kb * 64 + j * 16],
                                    sf[j], LDS_, wmma::mem_row_major);
        __syncthreads();
    }

    // Softmax (fp32, register-held), then P -> fp16 in place
    const int nk = L >> 5;   // 4 or 8
    for (int rr = 0; rr < 16; rr++) {
        int r = wid * 16 + rr;
        int t = qt * 128 + r;
        float* Srow = &Ss[r * LDS_];
        float p[8];
        float mx = -1e30f;
        for (int k = 0; k < nk; k++) {
            int c = lane + 32 * k;
            float s = (c <= t) ? Srow[c] : -1e30f;
            p[k] = s;
            mx = fmaxf(mx, s);
        }
#pragma unroll
        for (int o = 16; o; o >>= 1) mx = fmaxf(mx, __shfl_xor_sync(~0u, mx, o));
        float sum = 0.f;
        for (int k = 0; k < nk; k++) {
            float e = __expf(p[k] - mx);
            p[k] = e;
            sum += e;
        }
#pragma unroll
        for (int o = 16; o; o >>= 1) sum += __shfl_xor_sync(~0u, sum, o);
        float inv = 1.f / sum;
        __half* Hrow = (__half*)Srow;
        for (int k = 0; k < nk; k++)
            Hrow[lane + 32 * k] = __float2half_rn(p[k] * inv);
    }

    // Phase 2: O = P @ V
    HFragC of[4];
#pragma unroll
    for (int j = 0; j < 4; j++) wmma::fill_fragment(of[j], 0.0f);

    for (int kb = 0; kb <= kbmax; kb++) {
        __syncthreads();   // prior KVh readers done
#pragma unroll
        for (int i = 0; i < 4; i++) {
            int idx = tid + i * 256;
            int r = idx >> 4, c4 = idx & 15;
            float4 v = *(const float4*)&vp[(size_t)(kb * 64 + r) * D_ + c4 * 4];
            sth4(&KVh[r * 72 + c4 * 4], v);
        }
        __syncthreads();
#pragma unroll
        for (int kk = 0; kk < 4; kk++) {
            HFragA a;   // P rows, half view of Ss, stride 2*LDS_ halves
            wmma::load_matrix_sync(a, &Hs[(wid * 16) * (2 * LDS_) + kb * 64 + kk * 16],
                                   2 * LDS_);
#pragma unroll
            for (int j = 0; j < 4; j++) {
                HFragB bf;
                wmma::load_matrix_sync(bf, &KVh[(kk * 16) * 72 + j * 16], 72);
                wmma::mma_sync(of[j], a, bf, of[j]);
            }
        }
    }

    float* op = g_o + base + (size_t)(qt * 128 + wid * 16) * D_;
#pragma unroll
    for (int j = 0; j < 4; j++)
        wmma::store_matrix_sync(op + j * 16, of[j], D_, wmma::mem_row_major);
}

// ---------------------------------------------------------------------------
// Kernel 3: output projection. 128 thr, tile 128 x 64, K-tile 64 (one head),
// double-buffered fp16 smem, bias pre-loaded into acc. grid = (128, 6).
// ---------------------------------------------------------------------------
#define PROJ_SMEM_BYTES QKV_SMEM_BYTES

__global__ __launch_bounds__(128) void proj_kernel(const float* __restrict__ Wp,
                                                   const float* __restrict__ bp,
                                                   float* __restrict__ out) {
    extern __shared__ __half smh[];
    __half* Ah = smh;
    __half* Bh = smh + 2 * QA_H;
    float* bias_s = (float*)smh;   // transient, overwritten by stage(0,0)

    const int tid = threadIdx.x;
    const int wid = tid >> 5;
    const int m0 = blockIdx.x * 128;
    const int n0 = blockIdx.y * 64;
    const int b = m0 >> 8, t0 = m0 & 255;

    // Stage bias replicated across 16 rows (float), load into acc, then reuse smem
#pragma unroll
    for (int i = 0; i < 2; i++) {
        int idx = tid + i * 128;
        int r = idx >> 4, c4 = idx & 15;
        *(float4*)&bias_s[r * 68 + c4 * 4] = *(const float4*)&bp[n0 + c4 * 4];
    }
    __syncthreads();

    HFragC acc[2][4];
#pragma unroll
    for (int i = 0; i < 2; i++)
#pragma unroll
        for (int j = 0; j < 4; j++)
            wmma::load_matrix_sync(acc[i][j], &bias_s[j * 16], 68, wmma::mem_row_major);
    __syncthreads();   // acc loaded; smem free for staging

    auto stage = [&](int k0, int buf) {
        __half* Ab = Ah + buf * QA_H;
        __half* Bb = Bh + buf * QB_H;
        const int hh = k0 >> 6;    // K-tile == one head (64)
#pragma unroll
        for (int i = 0; i < 16; i++) {
            int idx = tid + i * 128;
            int r = idx >> 4, c4 = idx & 15;
            float4 v = *(const float4*)&g_o[(size_t)((b * H_ + hh) * T_ + t0 + r) * D_ + c4 * 4];
            sth4(&Ab[r * 72 + c4 * 4], v);
        }
#pragma unroll
        for (int i = 0; i < 8; i++) {
            int idx = tid + i * 128;
            int k = idx >> 4, c4 = idx & 15;
            float4 v = *(const float4*)&Wp[(size_t)(k0 + k) * C_ + n0 + c4 * 4];
            sth4(&Bb[k * 72 + c4 * 4], v);
        }
    };

    stage(0, 0);
    __syncthreads();

    for (int kt = 0; kt < 6; kt++) {
        const int cur = kt & 1;
        if (kt < 5) stage((kt + 1) * 64, cur ^ 1);
        const __half* Ab = Ah + cur * QA_H;
        const __half* Bb = Bh + cur * QB_H;
#pragma unroll
        for (int kk = 0; kk < 4; kk++) {
            HFragA a[2];
            HFragB bf[4];
#pragma unroll
            for (int i = 0; i < 2; i++)
                wmma::load_matrix_sync(a[i], &Ab[(wid * 32 + i * 16) * 72 + kk * 16], 72);
#pragma unroll
            for (int j = 0; j < 4; j++)
                wmma::load_matrix_sync(bf[j], &Bb[(kk * 16) * 72 + j * 16], 72);
#pragma unroll
            for (int i = 0; i < 2; i++)
#pragma unroll
                for (int j = 0; j < 4; j++)
                    wmma::mma_sync(acc[i][j], a[i], bf[j], acc[i][j]);
        }
        __syncthreads();
    }

#pragma unroll
    for (int i = 0; i < 2; i++)
#pragma unroll
        for (int j = 0; j < 4; j++) {
            float* op = out + (size_t)(m0 + wid * 32 + i * 16) * C_ + n0 + j * 16;
            wmma::store_matrix_sync(op, acc[i][j], C_, wmma::mem_row_major);
        }
}

// ---------------------------------------------------------------------------
extern "C" void kernel_launch(void* const* d_in, const int* in_sizes, int n_in,
                              void* d_out, int out_size) {
    const float* x  = (const float*)d_in[0];
    const float* Wq = (const float*)d_in[1];
    const float* Wk = (const float*)d_in[2];
    const float* Wv = (const float*)d_in[3];
    const float* Wp = (const float*)d_in[4];
    const float* bp = (const float*)d_in[5];
    float* out = (float*)d_out;

    cudaFuncSetAttribute(qkv_kernel, cudaFuncAttributeMaxDynamicSharedMemorySize,
                         QKV_SMEM_BYTES);
    cudaFuncSetAttribute(attn_kernel, cudaFuncAttributeMaxDynamicSharedMemorySize,
                         ATTN_SMEM_BYTES);
    cudaFuncSetAttribute(proj_kernel, cudaFuncAttributeMaxDynamicSharedMemorySize,
                         PROJ_SMEM_BYTES);

    qkv_kernel<<<dim3(M_ / 128, 3 * H_), 128, QKV_SMEM_BYTES>>>(x, Wq, Wk, Wv);
    attn_kernel<<<dim3(T_ / 128, H_, B_), 256, ATTN_SMEM_BYTES>>>();
    proj_kernel<<<dim3(M_ / 128, C_ / 64), 128, PROJ_SMEM_BYTES>>>(Wp, bp, out);
}

// round 6
// speedup vs baseline: 4.4726x; 1.1109x over previous
#include <cuda_runtime.h>
#include <cuda_fp16.h>
#include <mma.h>
using namespace nvcuda;

#define B_ 64
#define T_ 256
#define C_ 384
#define H_ 6
#define D_ 64
#define M_ (B_*T_)

// Scratch (allocation-free rule: __device__ globals)
__device__ float g_q[B_*H_*T_*D_];
__device__ float g_k[B_*H_*T_*D_];
__device__ float g_v[B_*H_*T_*D_];
__device__ float g_o[B_*H_*T_*D_];
__device__ __align__(16) __half g_xh[M_*C_];          // x in fp16
__device__ __align__(16) __half g_wh[3*H_*C_*D_];     // Wq|Wk|Wv in fp16
__device__ __align__(16) __half g_wph[C_*C_];         // Wp in fp16

typedef wmma::fragment<wmma::matrix_a, 16, 16, 16, __half, wmma::row_major> HFragA;
typedef wmma::fragment<wmma::matrix_b, 16, 16, 16, __half, wmma::row_major> HFragB;
typedef wmma::fragment<wmma::matrix_b, 16, 16, 16, __half, wmma::col_major> HFragBT;
typedef wmma::fragment<wmma::accumulator, 16, 16, 16, float> HFragC;

__device__ __forceinline__ void sth4(__half* dst, float4 v) {
    union { __half2 h[2]; uint2 u; } t;
    t.h[0] = __floats2half2_rn(v.x, v.y);
    t.h[1] = __floats2half2_rn(v.z, v.w);
    *(uint2*)dst = t.u;
}

// ---------------------------------------------------------------------------
// Prep: fp32 -> fp16 conversion (vectorized)
// ---------------------------------------------------------------------------
__global__ void f2h_kernel(const float4* __restrict__ src, uint2* __restrict__ dst, int n4) {
    int i = blockIdx.x * blockDim.x + threadIdx.x;
    if (i >= n4) return;
    float4 v = src[i];
    union { __half2 h[2]; uint2 u; } t;
    t.h[0] = __floats2half2_rn(v.x, v.y);
    t.h[1] = __floats2half2_rn(v.z, v.w);
    dst[i] = t.u;
}

// ---------------------------------------------------------------------------
// Kernel 1: fused QKV projection. 128 thr (4 warps, 2x2 of 64x64 warp tiles),
// CTA tile 128(M) x 128(N), K-tile 32, double-buffered fp16 smem. grid (128, 9).
// ---------------------------------------------------------------------------
#define QKA 40
#define QKB 136
#define QKV_A_H (128*QKA)
#define QKV_B_H (32*QKB)
#define QKV_SMEM_BYTES ((2*(QKV_A_H + QKV_B_H))*2)

__global__ __launch_bounds__(128) void qkv_kernel() {
    extern __shared__ __half smh[];
    __half* Ah = smh;                  // [2][128][QKA]
    __half* Bh = smh + 2 * QKV_A_H;    // [2][32][QKB]

    const int tid = threadIdx.x;
    const int wid = tid >> 5;
    const int wr = wid & 1;            // row half (64 rows)
    const int wc = wid >> 1;           // col half (64 cols)
    const int m0 = blockIdx.x * 128;
    const int by = blockIdx.y;         // 0..8
    const int mat = by / 3;
    const int nb = (by % 3) * 128;     // column offset in 384-wide per-mat output
    const __half* Wm = g_wh + (size_t)mat * H_ * C_ * D_;
    float* outp = (mat == 0 ? g_q : (mat == 1 ? g_k : g_v));

    HFragC acc[4][4];
#pragma unroll
    for (int i = 0; i < 4; i++)
#pragma unroll
        for (int j = 0; j < 4; j++) wmma::fill_fragment(acc[i][j], 0.0f);

    auto stage = [&](int k0, int buf) {
        __half* Ab = Ah + buf * QKV_A_H;
        __half* Bb = Bh + buf * QKV_B_H;
#pragma unroll
        for (int i = 0; i < 4; i++) {      // A: 128x32 halves
            int idx = tid + i * 128;
            int r = idx >> 2, c = idx & 3;
            *(uint4*)&Ab[r * QKA + c * 8] =
                *(const uint4*)&g_xh[(size_t)(m0 + r) * C_ + k0 + c * 8];
        }
#pragma unroll
        for (int i = 0; i < 4; i++) {      // B: 32x128 halves (head gather)
            int idx = tid + i * 128;
            int r = idx >> 4, c = idx & 15;
            int nm = nb + c * 8;
            int h = nm >> 6, d = nm & 63;
            *(uint4*)&Bb[r * QKB + c * 8] =
                *(const uint4*)&Wm[(size_t)h * C_ * D_ + (k0 + r) * D_ + d];
        }
    };

    stage(0, 0);
    __syncthreads();

    for (int kt = 0; kt < 12; kt++) {
        const int cur = kt & 1;
        if (kt < 11) stage((kt + 1) * 32, cur ^ 1);
        const __half* Ab = Ah + cur * QKV_A_H;
        const __half* Bb = Bh + cur * QKV_B_H;
#pragma unroll
        for (int kk = 0; kk < 2; kk++) {
            HFragA a[4];
            HFragB b[4];
#pragma unroll
            for (int i = 0; i < 4; i++)
                wmma::load_matrix_sync(a[i], &Ab[(wr * 64 + i * 16) * QKA + kk * 16], QKA);
#pragma unroll
            for (int j = 0; j < 4; j++)
                wmma::load_matrix_sync(b[j], &Bb[(kk * 16) * QKB + wc * 64 + j * 16], QKB);
#pragma unroll
            for (int i = 0; i < 4; i++)
#pragma unroll
                for (int j = 0; j < 4; j++)
                    wmma::mma_sync(acc[i][j], a[i], b[j], acc[i][j]);
        }
        __syncthreads();
    }

    const int b = m0 >> 8, t0 = m0 & 255;
#pragma unroll
    for (int i = 0; i < 4; i++)
#pragma unroll
        for (int j = 0; j < 4; j++) {
            int nm = nb + wc * 64 + j * 16;
            int h = nm >> 6, d0 = nm & 63;
            float* op = outp + (size_t)((b * H_ + h) * T_ + t0 + wr * 64 + i * 16) * D_ + d0;
            wmma::store_matrix_sync(op, acc[i][j], D_, wmma::mem_row_major);
        }
}

// ---------------------------------------------------------------------------
// Kernel 2: causal attention. 256 thr (8 warps, 4x2 of 32x32 warp tiles),
// 128-row q tile, fp32 S panel + in-place fp16 P. grid (2, 6, 64).
// ---------------------------------------------------------------------------
#define LDS_ 268
#define ATTN_KV_OFF (128*72)
#define ATTN_S_OFF  ((128*72 + 64*72)*2)
#define ATTN_SMEM_BYTES (ATTN_S_OFF + 128*LDS_*4)

__global__ __launch_bounds__(256) void attn_kernel() {
    extern __shared__ char smc[];
    __half* Qh  = (__half*)smc;                    // 128 x 72 (pre-scaled)
    __half* KVh = (__half*)smc + ATTN_KV_OFF;      // 64 x 72 (K then V)
    float*  Ss  = (float*)(smc + ATTN_S_OFF);      // 128 x LDS_
    __half* Hs  = (__half*)Ss;                     // half view, stride 2*LDS_

    const int qt = blockIdx.x;
    const int h  = blockIdx.y;
    const int b  = blockIdx.z;
    const size_t base = (size_t)((b * H_ + h) * T_) * D_;
    const float* qp = g_q + base + (size_t)qt * 128 * D_;
    const float* kp = g_k + base;
    const float* vp = g_v + base;

    const int tid = threadIdx.x;
    const int lane = tid & 31;
    const int wid = tid >> 5;
    const int wr = wid & 3;        // 32-row group
    const int wc = wid >> 2;       // 32-col group
    const int kbmax = 2 * qt + 1;
    const int L = (kbmax + 1) * 64;

    // Q tile (128x64), pre-scaled by 0.125
#pragma unroll
    for (int i = 0; i < 8; i++) {
        int idx = tid + i * 256;
        int r = idx >> 4, c4 = idx & 15;
        float4 v = *(const float4*)&qp[(size_t)r * D_ + c4 * 4];
        v.x *= 0.125f; v.y *= 0.125f; v.z *= 0.125f; v.w *= 0.125f;
        sth4(&Qh[r * 72 + c4 * 4], v);
    }
    __syncthreads();

    // Phase 1: S = (Q*scale) @ K^T
    for (int kb = 0; kb <= kbmax; kb++) {
#pragma unroll
        for (int i = 0; i < 4; i++) {
            int idx = tid + i * 256;
            int r = idx >> 4, c4 = idx & 15;
            float4 v = *(const float4*)&kp[(size_t)(kb * 64 + r) * D_ + c4 * 4];
            sth4(&KVh[r * 72 + c4 * 4], v);
        }
        __syncthreads();

        HFragC sf[2][2];
#pragma unroll
        for (int i = 0; i < 2; i++)
#pragma unroll
            for (int j = 0; j < 2; j++) wmma::fill_fragment(sf[i][j], 0.0f);
#pragma unroll
        for (int kk = 0; kk < 4; kk++) {
            HFragA a[2];
            HFragBT bt[2];
#pragma unroll
            for (int i = 0; i < 2; i++)
                wmma::load_matrix_sync(a[i], &Qh[(wr * 32 + i * 16) * 72 + kk * 16], 72);
#pragma unroll
            for (int j = 0; j < 2; j++)
                wmma::load_matrix_sync(bt[j], &KVh[(wc * 32 + j * 16) * 72 + kk * 16], 72);
#pragma unroll
            for (int i = 0; i < 2; i++)
#pragma unroll
                for (int j = 0; j < 2; j++)
                    wmma::mma_sync(sf[i][j], a[i], bt[j], sf[i][j]);
        }
#pragma unroll
        for (int i = 0; i < 2; i++)
#pragma unroll
            for (int j = 0; j < 2; j++)
                wmma::store_matrix_sync(
                    &Ss[(wr * 32 + i * 16) * LDS_ + kb * 64 + wc * 32 + j * 16],
                    sf[i][j], LDS_, wmma::mem_row_major);
        __syncthreads();
    }

    // Softmax (fp32, register-held), then P -> fp16 in place (16 rows/warp)
    const int nk = L >> 5;
    for (int rr = 0; rr < 16; rr++) {
        int r = wid * 16 + rr;
        int t = qt * 128 + r;
        float* Srow = &Ss[r * LDS_];
        float p[8];
        float mx = -1e30f;
        for (int k = 0; k < nk; k++) {
            int c = lane + 32 * k;
            float s = (c <= t) ? Srow[c] : -1e30f;
            p[k] = s;
            mx = fmaxf(mx, s);
        }
#pragma unroll
        for (int o = 16; o; o >>= 1) mx = fmaxf(mx, __shfl_xor_sync(~0u, mx, o));
        float sum = 0.f;
        for (int k = 0; k < nk; k++) {
            float e = __expf(p[k] - mx);
            p[k] = e;
            sum += e;
        }
#pragma unroll
        for (int o = 16; o; o >>= 1) sum += __shfl_xor_sync(~0u, sum, o);
        float inv = 1.f / sum;
        __half* Hrow = (__half*)Srow;
        for (int k = 0; k < nk; k++)
            Hrow[lane + 32 * k] = __float2half_rn(p[k] * inv);
    }

    // Phase 2: O = P @ V
    HFragC of[2][2];
#pragma unroll
    for (int i = 0; i < 2; i++)
#pragma unroll
        for (int j = 0; j < 2; j++) wmma::fill_fragment(of[i][j], 0.0f);

    for (int kb = 0; kb <= kbmax; kb++) {
        __syncthreads();   // prior KVh readers done (also orders P writes, 1st iter)
#pragma unroll
        for (int i = 0; i < 4; i++) {
            int idx = tid + i * 256;
            int r = idx >> 4, c4 = idx & 15;
            float4 v = *(const float4*)&vp[(size_t)(kb * 64 + r) * D_ + c4 * 4];
            sth4(&KVh[r * 72 + c4 * 4], v);
        }
        __syncthreads();
#pragma unroll
        for (int kk = 0; kk < 4; kk++) {
            HFragA a[2];
            HFragB bf[2];
#pragma unroll
            for (int i = 0; i < 2; i++)
                wmma::load_matrix_sync(
                    a[i], &Hs[(wr * 32 + i * 16) * (2 * LDS_) + kb * 64 + kk * 16],
                    2 * LDS_);
#pragma unroll
            for (int j = 0; j < 2; j++)
                wmma::load_matrix_sync(bf[j], &KVh[(kk * 16) * 72 + wc * 32 + j * 16], 72);
#pragma unroll
            for (int i = 0; i < 2; i++)
#pragma unroll
                for (int j = 0; j < 2; j++)
                    wmma::mma_sync(of[i][j], a[i], bf[j], of[i][j]);
        }
    }

    float* op = g_o + base + (size_t)(qt * 128) * D_;
#pragma unroll
    for (int i = 0; i < 2; i++)
#pragma unroll
        for (int j = 0; j < 2; j++)
            wmma::store_matrix_sync(op + (size_t)(wr * 32 + i * 16) * D_ + wc * 32 + j * 16,
                                    of[i][j], D_, wmma::mem_row_major);
}

// ---------------------------------------------------------------------------
// Kernel 3: output projection. 128 thr (2x2 of 64x64 warp tiles),
// CTA tile 128 x 128, K-tile 32, bias pre-loaded. grid (128, 3).
// ---------------------------------------------------------------------------
#define PROJ_SMEM_BYTES QKV_SMEM_BYTES

__global__ __launch_bounds__(128) void proj_kernel(const float* __restrict__ bp,
                                                   float* __restrict__ out) {
    extern __shared__ __half smh[];
    __half* Ah = smh;
    __half* Bh = smh + 2 * QKV_A_H;
    float* bias_s = (float*)smh;   // transient [16][136], overwritten by stage(0,0)

    const int tid = threadIdx.x;
    const int wid = tid >> 5;
    const int wr = wid & 1, wc = wid >> 1;
    const int m0 = blockIdx.x * 128;
    const int n0 = blockIdx.y * 128;
    const int b = m0 >> 8, t0 = m0 & 255;

    // Stage bias replicated across 16 rows, load into acc, then free smem
#pragma unroll
    for (int i = 0; i < 4; i++) {
        int idx = tid + i * 128;
        int r = idx >> 5, c4 = idx & 31;
        *(float4*)&bias_s[r * 136 + c4 * 4] = *(const float4*)&bp[n0 + c4 * 4];
    }
    __syncthreads();

    HFragC acc[4][4];
#pragma unroll
    for (int i = 0; i < 4; i++)
#pragma unroll
        for (int j = 0; j < 4; j++)
            wmma::load_matrix_sync(acc[i][j], &bias_s[wc * 64 + j * 16], 136,
                                   wmma::mem_row_major);
    __syncthreads();

    auto stage = [&](int k0, int buf) {
        __half* Ab = Ah + buf * QKV_A_H;
        __half* Bb = Bh + buf * QKV_B_H;
        const int hh = k0 >> 6, d0 = k0 & 63;
#pragma unroll
        for (int i = 0; i < 8; i++) {      // A: gather 128x32 fp32 -> fp16
            int idx = tid + i * 128;
            int r = idx >> 3, c = idx & 7;
            float4 v = *(const float4*)&g_o[(size_t)((b * H_ + hh) * T_ + t0 + r) * D_ + d0 + c * 4];
            sth4(&Ab[r * QKA + c * 4], v);
        }
#pragma unroll
        for (int i = 0; i < 4; i++) {      // B: 32x128 fp16 copy
            int idx = tid + i * 128;
            int r = idx >> 4, c = idx & 15;
            *(uint4*)&Bb[r * QKB + c * 8] =
                *(const uint4*)&g_wph[(size_t)(k0 + r) * C_ + n0 + c * 8];
        }
    };

    stage(0, 0);
    __syncthreads();

    for (int kt = 0; kt < 12; kt++) {
        const int cur = kt & 1;
        if (kt < 11) stage((kt + 1) * 32, cur ^ 1);
        const __half* Ab = Ah + cur * QKV_A_H;
        const __half* Bb = Bh + cur * QKV_B_H;
#pragma unroll
        for (int kk = 0; kk < 2; kk++) {
            HFragA a[4];
            HFragB bf[4];
#pragma unroll
            for (int i = 0; i < 4; i++)
                wmma::load_matrix_sync(a[i], &Ab[(wr * 64 + i * 16) * QKA + kk * 16], QKA);
#pragma unroll
            for (int j = 0; j < 4; j++)
                wmma::load_matrix_sync(bf[j], &Bb[(kk * 16) * QKB + wc * 64 + j * 16], QKB);
#pragma unroll
            for (int i = 0; i < 4; i++)
#pragma unroll
                for (int j = 0; j < 4; j++)
                    wmma::mma_sync(acc[i][j], a[i], bf[j], acc[i][j]);
        }
        __syncthreads();
    }

#pragma unroll
    for (int i = 0; i < 4; i++)
#pragma unroll
        for (int j = 0; j < 4; j++) {
            float* op = out + (size_t)(m0 + wr * 64 + i * 16) * C_ + n0 + wc * 64 + j * 16;
            wmma::store_matrix_sync(op, acc[i][j], C_, wmma::mem_row_major);
        }
}

// ---------------------------------------------------------------------------
extern "C" void kernel_launch(void* const* d_in, const int* in_sizes, int n_in,
                              void* d_out, int out_size) {
    const float* x  = (const float*)d_in[0];
    const float* Wq = (const float*)d_in[1];
    const float* Wk = (const float*)d_in[2];
    const float* Wv = (const float*)d_in[3];
    const float* Wp = (const float*)d_in[4];
    const float* bp = (const float*)d_in[5];
    float* out = (float*)d_out;

    void *xh_p, *wh_p, *wph_p;
    cudaGetSymbolAddress(&xh_p, g_xh);
    cudaGetSymbolAddress(&wh_p, g_wh);
    cudaGetSymbolAddress(&wph_p, g_wph);
    __half* xh  = (__half*)xh_p;
    __half* wh  = (__half*)wh_p;
    __half* wph = (__half*)wph_p;

    cudaFuncSetAttribute(qkv_kernel, cudaFuncAttributeMaxDynamicSharedMemorySize,
                         QKV_SMEM_BYTES);
    cudaFuncSetAttribute(attn_kernel, cudaFuncAttributeMaxDynamicSharedMemorySize,
                         ATTN_SMEM_BYTES);
    cudaFuncSetAttribute(proj_kernel, cudaFuncAttributeMaxDynamicSharedMemorySize,
                         PROJ_SMEM_BYTES);

    const int WSZ = H_ * C_ * D_;            // 147456
    f2h_kernel<<<(M_*C_/4 + 255)/256, 256>>>((const float4*)x,  (uint2*)xh, M_*C_/4);
    f2h_kernel<<<(WSZ/4 + 255)/256, 256>>>((const float4*)Wq, (uint2*)(wh + 0*WSZ), WSZ/4);
    f2h_kernel<<<(WSZ/4 + 255)/256, 256>>>((const float4*)Wk, (uint2*)(wh + 1*WSZ), WSZ/4);
    f2h_kernel<<<(WSZ/4 + 255)/256, 256>>>((const float4*)Wv, (uint2*)(wh + 2*WSZ), WSZ/4);
    f2h_kernel<<<(C_*C_/4 + 255)/256, 256>>>((const float4*)Wp, (uint2*)wph, C_*C_/4);

    qkv_kernel<<<dim3(M_ / 128, 9), 128, QKV_SMEM_BYTES>>>();
    attn_kernel<<<dim3(T_ / 128, H_, B_), 256, ATTN_SMEM_BYTES>>>();
    proj_kernel<<<dim3(M_ / 128, C_ / 128), 128, PROJ_SMEM_BYTES>>>(bp, out);
}

// round 7
// speedup vs baseline: 5.0339x; 1.1255x over previous
#include <cuda_runtime.h>
#include <cuda_fp16.h>
#include <mma.h>
using namespace nvcuda;

#define B_ 64
#define T_ 256
#define C_ 384
#define H_ 6
#define D_ 64
#define M_ (B_*T_)

// Scratch (allocation-free rule: __device__ globals) — all fp16 now
__device__ __align__(16) __half g_qh[B_*H_*T_*D_];   // pre-scaled by 0.125
__device__ __align__(16) __half g_kh[B_*H_*T_*D_];
__device__ __align__(16) __half g_vh[B_*H_*T_*D_];
__device__ __align__(16) __half g_oh[B_*H_*T_*D_];
__device__ __align__(16) __half g_xh[M_*C_];
__device__ __align__(16) __half g_wh[3*H_*C_*D_];
__device__ __align__(16) __half g_wph[C_*C_];

typedef wmma::fragment<wmma::matrix_a, 16, 16, 16, __half, wmma::row_major> HFragA;
typedef wmma::fragment<wmma::matrix_b, 16, 16, 16, __half, wmma::row_major> HFragB;
typedef wmma::fragment<wmma::matrix_b, 16, 16, 16, __half, wmma::col_major> HFragBT;
typedef wmma::fragment<wmma::accumulator, 16, 16, 16, float> HFragC;

__device__ __forceinline__ void sth4(__half* dst, float4 v) {
    union { __half2 h[2]; uint2 u; } t;
    t.h[0] = __floats2half2_rn(v.x, v.y);
    t.h[1] = __floats2half2_rn(v.z, v.w);
    *(uint2*)dst = t.u;
}

// Store one fp32 16x16 acc fragment as fp16 to global, via per-warp smem scratch
// (scratch: 16*20 floats, float4-aligned stride). dst row stride = ldd halves.
__device__ __forceinline__ void frag2half(__half* dst, int ldd, const HFragC& f,
                                          float* sc, int lane, float scale) {
    wmma::store_matrix_sync(sc, f, 20, wmma::mem_row_major);
    __syncwarp();
#pragma unroll
    for (int i = lane; i < 64; i += 32) {      // 64 groups of 4 elems
        int r = i >> 2, c4 = i & 3;
        float4 v = *(float4*)&sc[r * 20 + c4 * 4];
        v.x *= scale; v.y *= scale; v.z *= scale; v.w *= scale;
        sth4(&dst[(size_t)r * ldd + c4 * 4], v);
    }
    __syncwarp();
}

// ---------------------------------------------------------------------------
// Prep: one segmented fp32 -> fp16 conversion kernel (x | Wq | Wk | Wv | Wp)
// ---------------------------------------------------------------------------
#define NX4 (M_*C_/4)          // 1572864
#define NW4 (H_*C_*D_/4)       // 36864
#define NTOT4 (NX4 + 4*NW4)

__global__ void prep_kernel(const float4* __restrict__ x,
                            const float4* __restrict__ wq,
                            const float4* __restrict__ wk,
                            const float4* __restrict__ wv,
                            const float4* __restrict__ wp) {
    int i = blockIdx.x * blockDim.x + threadIdx.x;
    if (i >= NTOT4) return;
    const float4* src;
    uint2* dst;
    int off;
    if (i < NX4) {
        src = x; dst = (uint2*)g_xh; off = i;
    } else {
        int j = i - NX4;
        int seg = j / NW4;
        off = j - seg * NW4;
        if (seg == 0)      { src = wq; dst = (uint2*)(g_wh + 0*(size_t)H_*C_*D_); }
        else if (seg == 1) { src = wk; dst = (uint2*)(g_wh + 1*(size_t)H_*C_*D_); }
        else if (seg == 2) { src = wv; dst = (uint2*)(g_wh + 2*(size_t)H_*C_*D_); }
        else               { src = wp; dst = (uint2*)g_wph; }
    }
    float4 v = src[off];
    union { __half2 h[2]; uint2 u; } t;
    t.h[0] = __floats2half2_rn(v.x, v.y);
    t.h[1] = __floats2half2_rn(v.z, v.w);
    dst[off] = t.u;
}

// ---------------------------------------------------------------------------
// Kernel 1: fused QKV projection. 128 thr (2x2 of 64x64 warp tiles),
// CTA 128x128, K-tile 32, double-buffered fp16 smem, fp16 epilogue. grid (128, 9).
// ---------------------------------------------------------------------------
#define QKA 40
#define QKB 136
#define QKV_A_H (128*QKA)
#define QKV_B_H (32*QKB)
#define QKV_SCR_OFF (2*(QKV_A_H + QKV_B_H))              // halves
#define QKV_SMEM_BYTES (QKV_SCR_OFF*2 + 4*320*4)

__global__ __launch_bounds__(128) void qkv_kernel() {
    extern __shared__ __half smh[];
    __half* Ah = smh;                  // [2][128][QKA]
    __half* Bh = smh + 2 * QKV_A_H;    // [2][32][QKB]
    float* scr = (float*)(smh + QKV_SCR_OFF);

    const int tid = threadIdx.x;
    const int lane = tid & 31;
    const int wid = tid >> 5;
    const int wr = wid & 1;
    const int wc = wid >> 1;
    const int m0 = blockIdx.x * 128;
    const int by = blockIdx.y;         // 0..8
    const int mat = by / 3;
    const int nb = (by % 3) * 128;
    const __half* Wm = g_wh + (size_t)mat * H_ * C_ * D_;
    __half* outp = (mat == 0 ? g_qh : (mat == 1 ? g_kh : g_vh));
    const float oscale = (mat == 0) ? 0.125f : 1.0f;

    HFragC acc[4][4];
#pragma unroll
    for (int i = 0; i < 4; i++)
#pragma unroll
        for (int j = 0; j < 4; j++) wmma::fill_fragment(acc[i][j], 0.0f);

    auto stage = [&](int k0, int buf) {
        __half* Ab = Ah + buf * QKV_A_H;
        __half* Bb = Bh + buf * QKV_B_H;
#pragma unroll
        for (int i = 0; i < 4; i++) {      // A: 128x32 halves
            int idx = tid + i * 128;
            int r = idx >> 2, c = idx & 3;
            *(uint4*)&Ab[r * QKA + c * 8] =
                *(const uint4*)&g_xh[(size_t)(m0 + r) * C_ + k0 + c * 8];
        }
#pragma unroll
        for (int i = 0; i < 4; i++) {      // B: 32x128 halves (head gather)
            int idx = tid + i * 128;
            int r = idx >> 4, c = idx & 15;
            int nm = nb + c * 8;
            int h = nm >> 6, d = nm & 63;
            *(uint4*)&Bb[r * QKB + c * 8] =
                *(const uint4*)&Wm[(size_t)h * C_ * D_ + (k0 + r) * D_ + d];
        }
    };

    stage(0, 0);
    __syncthreads();

    for (int kt = 0; kt < 12; kt++) {
        const int cur = kt & 1;
        if (kt < 11) stage((kt + 1) * 32, cur ^ 1);
        const __half* Ab = Ah + cur * QKV_A_H;
        const __half* Bb = Bh + cur * QKV_B_H;
#pragma unroll
        for (int kk = 0; kk < 2; kk++) {
            HFragA a[4];
            HFragB b[4];
#pragma unroll
            for (int i = 0; i < 4; i++)
                wmma::load_matrix_sync(a[i], &Ab[(wr * 64 + i * 16) * QKA + kk * 16], QKA);
#pragma unroll
            for (int j = 0; j < 4; j++)
                wmma::load_matrix_sync(b[j], &Bb[(kk * 16) * QKB + wc * 64 + j * 16], QKB);
#pragma unroll
            for (int i = 0; i < 4; i++)
#pragma unroll
                for (int j = 0; j < 4; j++)
                    wmma::mma_sync(acc[i][j], a[i], b[j], acc[i][j]);
        }
        __syncthreads();
    }

    const int b = m0 >> 8, t0 = m0 & 255;
    float* mysc = scr + wid * 320;
#pragma unroll
    for (int i = 0; i < 4; i++)
#pragma unroll
        for (int j = 0; j < 4; j++) {
            int nm = nb + wc * 64 + j * 16;
            int h = nm >> 6, d0 = nm & 63;
            __half* op = outp + (size_t)((b * H_ + h) * T_ + t0 + wr * 64 + i * 16) * D_ + d0;
            frag2half(op, D_, acc[i][j], mysc, lane, oscale);
        }
}

// ---------------------------------------------------------------------------
// Kernel 2: causal attention. 256 thr (4x2 of 32x32 warp tiles), 128-row q
// tile, fp16 scratch in/out, fp32 S panel + in-place fp16 P. grid (2, 6, 64).
// ---------------------------------------------------------------------------
#define LDS_ 268
#define ATTN_KV_OFF (128*72)
#define ATTN_S_OFF  ((128*72 + 64*72)*2)
#define ATTN_SCR_OFF (ATTN_S_OFF + 128*LDS_*4)
#define ATTN_SMEM_BYTES (ATTN_SCR_OFF + 8*320*4)

__global__ __launch_bounds__(256) void attn_kernel() {
    extern __shared__ char smc[];
    __half* Qh  = (__half*)smc;                    // 128 x 72
    __half* KVh = (__half*)smc + ATTN_KV_OFF;      // 64 x 72 (K then V)
    float*  Ss  = (float*)(smc + ATTN_S_OFF);      // 128 x LDS_
    __half* Hs  = (__half*)Ss;                     // half view
    float*  scr = (float*)(smc + ATTN_SCR_OFF);

    const int qt = blockIdx.x;
    const int h  = blockIdx.y;
    const int b  = blockIdx.z;
    const size_t base = (size_t)((b * H_ + h) * T_) * D_;
    const __half* qp = g_qh + base + (size_t)qt * 128 * D_;
    const __half* kp = g_kh + base;
    const __half* vp = g_vh + base;

    const int tid = threadIdx.x;
    const int lane = tid & 31;
    const int wid = tid >> 5;
    const int wr = wid & 3;
    const int wc = wid >> 2;
    const int kbmax = 2 * qt + 1;
    const int L = (kbmax + 1) * 64;

    // Q tile (128x64) — pure copy (already scaled in qkv epilogue)
#pragma unroll
    for (int i = 0; i < 4; i++) {
        int idx = tid + i * 256;
        int r = idx >> 3, c = idx & 7;
        *(uint4*)&Qh[r * 72 + c * 8] = *(const uint4*)&qp[(size_t)r * D_ + c * 8];
    }
    __syncthreads();

    // Phase 1: S = Q @ K^T
    for (int kb = 0; kb <= kbmax; kb++) {
#pragma unroll
        for (int i = 0; i < 2; i++) {
            int idx = tid + i * 256;
            int r = idx >> 3, c = idx & 7;
            *(uint4*)&KVh[r * 72 + c * 8] =
                *(const uint4*)&kp[(size_t)(kb * 64 + r) * D_ + c * 8];
        }
        __syncthreads();

        HFragC sf[2][2];
#pragma unroll
        for (int i = 0; i < 2; i++)
#pragma unroll
            for (int j = 0; j < 2; j++) wmma::fill_fragment(sf[i][j], 0.0f);
#pragma unroll
        for (int kk = 0; kk < 4; kk++) {
            HFragA a[2];
            HFragBT bt[2];
#pragma unroll
            for (int i = 0; i < 2; i++)
                wmma::load_matrix_sync(a[i], &Qh[(wr * 32 + i * 16) * 72 + kk * 16], 72);
#pragma unroll
            for (int j = 0; j < 2; j++)
                wmma::load_matrix_sync(bt[j], &KVh[(wc * 32 + j * 16) * 72 + kk * 16], 72);
#pragma unroll
            for (int i = 0; i < 2; i++)
#pragma unroll
                for (int j = 0; j < 2; j++)
                    wmma::mma_sync(sf[i][j], a[i], bt[j], sf[i][j]);
        }
#pragma unroll
        for (int i = 0; i < 2; i++)
#pragma unroll
            for (int j = 0; j < 2; j++)
                wmma::store_matrix_sync(
                    &Ss[(wr * 32 + i * 16) * LDS_ + kb * 64 + wc * 32 + j * 16],
                    sf[i][j], LDS_, wmma::mem_row_major);
        __syncthreads();
    }

    // Softmax (fp32, register-held), then P -> fp16 in place (16 rows/warp)
    const int nk = L >> 5;
    for (int rr = 0; rr < 16; rr++) {
        int r = wid * 16 + rr;
        int t = qt * 128 + r;
        float* Srow = &Ss[r * LDS_];
        float p[8];
        float mx = -1e30f;
        for (int k = 0; k < nk; k++) {
            int c = lane + 32 * k;
            float s = (c <= t) ? Srow[c] : -1e30f;
            p[k] = s;
            mx = fmaxf(mx, s);
        }
#pragma unroll
        for (int o = 16; o; o >>= 1) mx = fmaxf(mx, __shfl_xor_sync(~0u, mx, o));
        float sum = 0.f;
        for (int k = 0; k < nk; k++) {
            float e = __expf(p[k] - mx);
            p[k] = e;
            sum += e;
        }
#pragma unroll
        for (int o = 16; o; o >>= 1) sum += __shfl_xor_sync(~0u, sum, o);
        float inv = 1.f / sum;
        __half* Hrow = (__half*)Srow;
        for (int k = 0; k < nk; k++)
            Hrow[lane + 32 * k] = __float2half_rn(p[k] * inv);
    }

    // Phase 2: O = P @ V
    HFragC of[2][2];
#pragma unroll
    for (int i = 0; i < 2; i++)
#pragma unroll
        for (int j = 0; j < 2; j++) wmma::fill_fragment(of[i][j], 0.0f);

    for (int kb = 0; kb <= kbmax; kb++) {
        __syncthreads();
#pragma unroll
        for (int i = 0; i < 2; i++) {
            int idx = tid + i * 256;
            int r = idx >> 3, c = idx & 7;
            *(uint4*)&KVh[r * 72 + c * 8] =
                *(const uint4*)&vp[(size_t)(kb * 64 + r) * D_ + c * 8];
        }
        __syncthreads();
#pragma unroll
        for (int kk = 0; kk < 4; kk++) {
            HFragA a[2];
            HFragB bf[2];
#pragma unroll
            for (int i = 0; i < 2; i++)
                wmma::load_matrix_sync(
                    a[i], &Hs[(wr * 32 + i * 16) * (2 * LDS_) + kb * 64 + kk * 16],
                    2 * LDS_);
#pragma unroll
            for (int j = 0; j < 2; j++)
                wmma::load_matrix_sync(bf[j], &KVh[(kk * 16) * 72 + wc * 32 + j * 16], 72);
#pragma unroll
            for (int i = 0; i < 2; i++)
#pragma unroll
                for (int j = 0; j < 2; j++)
                    wmma::mma_sync(of[i][j], a[i], bf[j], of[i][j]);
        }
    }

    __half* op = g_oh + base + (size_t)(qt * 128) * D_;
    float* mysc = scr + wid * 320;
#pragma unroll
    for (int i = 0; i < 2; i++)
#pragma unroll
        for (int j = 0; j < 2; j++)
            frag2half(op + (size_t)(wr * 32 + i * 16) * D_ + wc * 32 + j * 16,
                      D_, of[i][j], mysc, lane, 1.0f);
}

// ---------------------------------------------------------------------------
// Kernel 3: output projection. 128 thr (2x2 of 64x64 warp tiles),
// CTA 128 x 128, K-tile 32, bias pre-loaded, fp32 out. grid (128, 3).
// ---------------------------------------------------------------------------
#define PROJ_SMEM_BYTES (QKV_SCR_OFF*2)

__global__ __launch_bounds__(128) void proj_kernel(const float* __restrict__ bp,
                                                   float* __restrict__ out) {
    extern __shared__ __half smh[];
    __half* Ah = smh;
    __half* Bh = smh + 2 * QKV_A_H;
    float* bias_s = (float*)smh;   // transient [16][136], overwritten by stage(0,0)

    const int tid = threadIdx.x;
    const int wid = tid >> 5;
    const int wr = wid & 1, wc = wid >> 1;
    const int m0 = blockIdx.x * 128;
    const int n0 = blockIdx.y * 128;
    const int b = m0 >> 8, t0 = m0 & 255;

#pragma unroll
    for (int i = 0; i < 4; i++) {
        int idx = tid + i * 128;
        int r = idx >> 5, c4 = idx & 31;
        *(float4*)&bias_s[r * 136 + c4 * 4] = *(const float4*)&bp[n0 + c4 * 4];
    }
    __syncthreads();

    HFragC acc[4][4];
#pragma unroll
    for (int i = 0; i < 4; i++)
#pragma unroll
        for (int j = 0; j < 4; j++)
            wmma::load_matrix_sync(acc[i][j], &bias_s[wc * 64 + j * 16], 136,
                                   wmma::mem_row_major);
    __syncthreads();

    auto stage = [&](int k0, int buf) {
        __half* Ab = Ah + buf * QKV_A_H;
        __half* Bb = Bh + buf * QKV_B_H;
        const int hh = k0 >> 6, d0 = k0 & 63;
#pragma unroll
        for (int i = 0; i < 4; i++) {      // A: 128x32 halves, pure copy from g_oh
            int idx = tid + i * 128;
            int r = idx >> 2, c = idx & 3;
            *(uint4*)&Ab[r * QKA + c * 8] =
                *(const uint4*)&g_oh[(size_t)((b * H_ + hh) * T_ + t0 + r) * D_ + d0 + c * 8];
        }
#pragma unroll
        for (int i = 0; i < 4; i++) {      // B: 32x128 halves
            int idx = tid + i * 128;
            int r = idx >> 4, c = idx & 15;
            *(uint4*)&Bb[r * QKB + c * 8] =
                *(const uint4*)&g_wph[(size_t)(k0 + r) * C_ + n0 + c * 8];
        }
    };

    stage(0, 0);
    __syncthreads();

    for (int kt = 0; kt < 12; kt++) {
        const int cur = kt & 1;
        if (kt < 11) stage((kt + 1) * 32, cur ^ 1);
        const __half* Ab = Ah + cur * QKV_A_H;
        const __half* Bb = Bh + cur * QKV_B_H;
#pragma unroll
        for (int kk = 0; kk < 2; kk++) {
            HFragA a[4];
            HFragB bf[4];
#pragma unroll
            for (int i = 0; i < 4; i++)
                wmma::load_matrix_sync(a[i], &Ab[(wr * 64 + i * 16) * QKA + kk * 16], QKA);
#pragma unroll
            for (int j = 0; j < 4; j++)
                wmma::load_matrix_sync(bf[j], &Bb[(kk * 16) * QKB + wc * 64 + j * 16], QKB);
#pragma unroll
            for (int i = 0; i < 4; i++)
#pragma unroll
                for (int j = 0; j < 4; j++)
                    wmma::mma_sync(acc[i][j], a[i], bf[j], acc[i][j]);
        }
        __syncthreads();
    }

#pragma unroll
    for (int i = 0; i < 4; i++)
#pragma unroll
        for (int j = 0; j < 4; j++) {
            float* op = out + (size_t)(m0 + wr * 64 + i * 16) * C_ + n0 + wc * 64 + j * 16;
            wmma::store_matrix_sync(op, acc[i][j], C_, wmma::mem_row_major);
        }
}

// ---------------------------------------------------------------------------
extern "C" void kernel_launch(void* const* d_in, const int* in_sizes, int n_in,
                              void* d_out, int out_size) {
    const float* x  = (const float*)d_in[0];
    const float* Wq = (const float*)d_in[1];
    const float* Wk = (const float*)d_in[2];
    const float* Wv = (const float*)d_in[3];
    const float* Wp = (const float*)d_in[4];
    const float* bp = (const float*)d_in[5];
    float* out = (float*)d_out;

    cudaFuncSetAttribute(qkv_kernel, cudaFuncAttributeMaxDynamicSharedMemorySize,
                         QKV_SMEM_BYTES);
    cudaFuncSetAttribute(attn_kernel, cudaFuncAttributeMaxDynamicSharedMemorySize,
                         ATTN_SMEM_BYTES);
    cudaFuncSetAttribute(proj_kernel, cudaFuncAttributeMaxDynamicSharedMemorySize,
                         PROJ_SMEM_BYTES);

    prep_kernel<<<(NTOT4 + 255)/256, 256>>>((const float4*)x, (const float4*)Wq,
                                            (const float4*)Wk, (const float4*)Wv,
                                            (const float4*)Wp);
    qkv_kernel<<<dim3(M_ / 128, 9), 128, QKV_SMEM_BYTES>>>();
    attn_kernel<<<dim3(T_ / 128, H_, B_), 256, ATTN_SMEM_BYTES>>>();
    proj_kernel<<<dim3(M_ / 128, C_ / 128), 128, PROJ_SMEM_BYTES>>>(bp, out);
}

// round 9
// speedup vs baseline: 5.3877x; 1.0703x over previous
#include <cuda_runtime.h>
#include <cuda_fp16.h>
#include <mma.h>
using namespace nvcuda;

#define B_ 64
#define T_ 256
#define C_ 384
#define H_ 6
#define D_ 64
#define M_ (B_*T_)

// Scratch (allocation-free rule: __device__ globals) — fp16
__device__ __align__(16) __half g_qh[B_*H_*T_*D_];   // pre-scaled by 0.125
__device__ __align__(16) __half g_kh[B_*H_*T_*D_];
__device__ __align__(16) __half g_vh[B_*H_*T_*D_];
__device__ __align__(16) __half g_oh[B_*H_*T_*D_];
__device__ __align__(16) __half g_xh[M_*C_];
__device__ __align__(16) __half g_wh[3*H_*C_*D_];
__device__ __align__(16) __half g_wph[C_*C_];

typedef wmma::fragment<wmma::matrix_a, 16, 16, 16, __half, wmma::row_major> HFragA;
typedef wmma::fragment<wmma::matrix_b, 16, 16, 16, __half, wmma::row_major> HFragB;
typedef wmma::fragment<wmma::matrix_b, 16, 16, 16, __half, wmma::col_major> HFragBT;
typedef wmma::fragment<wmma::accumulator, 16, 16, 16, float> HFragC;

__device__ __forceinline__ void cp16(void* sdst, const void* gsrc) {
    unsigned a = (unsigned)__cvta_generic_to_shared(sdst);
    asm volatile("cp.async.cg.shared.global [%0], [%1], 16;" :: "r"(a), "l"(gsrc));
}
__device__ __forceinline__ void cp_commit() { asm volatile("cp.async.commit_group;"); }
template<int N> __device__ __forceinline__ void cp_wait() {
    asm volatile("cp.async.wait_group %0;" :: "n"(N));
}

__device__ __forceinline__ void sth4(__half* dst, float4 v) {
    union { __half2 h[2]; uint2 u; } t;
    t.h[0] = __floats2half2_rn(v.x, v.y);
    t.h[1] = __floats2half2_rn(v.z, v.w);
    *(uint2*)dst = t.u;
}

// Store fp32 16x16 acc fragment as fp16 to global via per-warp smem scratch
__device__ __forceinline__ void frag2half(__half* dst, int ldd, const HFragC& f,
                                          float* sc, int lane, float scale) {
    wmma::store_matrix_sync(sc, f, 20, wmma::mem_row_major);
    __syncwarp();
#pragma unroll
    for (int i = lane; i < 64; i += 32) {
        int r = i >> 2, c4 = i & 3;
        float4 v = *(float4*)&sc[r * 20 + c4 * 4];
        v.x *= scale; v.y *= scale; v.z *= scale; v.w *= scale;
        sth4(&dst[(size_t)r * ldd + c4 * 4], v);
    }
    __syncwarp();
}

// ---------------------------------------------------------------------------
// Prep: one segmented fp32 -> fp16 conversion kernel (x | Wq | Wk | Wv | Wp)
// ---------------------------------------------------------------------------
#define NX4 (M_*C_/4)
#define NW4 (H_*C_*D_/4)
#define NTOT4 (NX4 + 4*NW4)

__global__ void prep_kernel(const float4* __restrict__ x,
                            const float4* __restrict__ wq,
                            const float4* __restrict__ wk,
                            const float4* __restrict__ wv,
                            const float4* __restrict__ wp) {
    int i = blockIdx.x * blockDim.x + threadIdx.x;
    if (i >= NTOT4) return;
    const float4* src;
    uint2* dst;
    int off;
    if (i < NX4) {
        src = x; dst = (uint2*)g_xh; off = i;
    } else {
        int j = i - NX4;
        int seg = j / NW4;
        off = j - seg * NW4;
        if (seg == 0)      { src = wq; dst = (uint2*)(g_wh + 0*(size_t)H_*C_*D_); }
        else if (seg == 1) { src = wk; dst = (uint2*)(g_wh + 1*(size_t)H_*C_*D_); }
        else if (seg == 2) { src = wv; dst = (uint2*)(g_wh + 2*(size_t)H_*C_*D_); }
        else               { src = wp; dst = (uint2*)g_wph; }
    }
    float4 v = src[off];
    union { __half2 h[2]; uint2 u; } t;
    t.h[0] = __floats2half2_rn(v.x, v.y);
    t.h[1] = __floats2half2_rn(v.z, v.w);
    dst[off] = t.u;
}

// ---------------------------------------------------------------------------
// Kernel 1: fused QKV projection. 256 thr (4x2 grid of 32x64 warp tiles),
// CTA 128x128, K-tile 32, cp.async double-buffered. grid (128, 9).
// ---------------------------------------------------------------------------
#define QKA 40
#define QKB 136
#define QKV_A_H (128*QKA)
#define QKV_B_H (32*QKB)
#define QKV_SCR_OFF (2*(QKV_A_H + QKV_B_H))   // halves
#define QKV_SMEM_BYTES (QKV_SCR_OFF*2 + 8*320*4)

__global__ __launch_bounds__(256) void qkv_kernel() {
    extern __shared__ __half smh[];
    __half* Ah = smh;                  // [2][128][QKA]
    __half* Bh = smh + 2 * QKV_A_H;    // [2][32][QKB]
    float* scr = (float*)(smh + QKV_SCR_OFF);

    const int tid = threadIdx.x;
    const int lane = tid & 31;
    const int wid = tid >> 5;
    const int wr = wid & 3;            // 32-row group
    const int wc = wid >> 2;           // 64-col group
    const int m0 = blockIdx.x * 128;
    const int by = blockIdx.y;         // 0..8
    const int mat = by / 3;
    const int nb = (by % 3) * 128;
    const __half* Wm = g_wh + (size_t)mat * H_ * C_ * D_;
    __half* outp = (mat == 0 ? g_qh : (mat == 1 ? g_kh : g_vh));
    const float oscale = (mat == 0) ? 0.125f : 1.0f;

    HFragC acc[2][4];
#pragma unroll
    for (int i = 0; i < 2; i++)
#pragma unroll
        for (int j = 0; j < 4; j++) wmma::fill_fragment(acc[i][j], 0.0f);

    auto stage = [&](int k0, int buf) {
        __half* Ab = Ah + buf * QKV_A_H;
        __half* Bb = Bh + buf * QKV_B_H;
#pragma unroll
        for (int i = 0; i < 2; i++) {      // A: 128x32 halves = 512 uint4
            int idx = tid + i * 256;
            int r = idx >> 2, c = idx & 3;
            cp16(&Ab[r * QKA + c * 8], &g_xh[(size_t)(m0 + r) * C_ + k0 + c * 8]);
        }
#pragma unroll
        for (int i = 0; i < 2; i++) {      // B: 32x128 halves (head gather)
            int idx = tid + i * 256;
            int r = idx >> 4, c = idx & 15;
            int nm = nb + c * 8;
            int h = nm >> 6, d = nm & 63;
            cp16(&Bb[r * QKB + c * 8], &Wm[(size_t)h * C_ * D_ + (k0 + r) * D_ + d]);
        }
    };

    stage(0, 0);
    cp_commit();

    for (int kt = 0; kt < 12; kt++) {
        const int cur = kt & 1;
        if (kt < 11) { stage((kt + 1) * 32, cur ^ 1); cp_commit(); cp_wait<1>(); }
        else cp_wait<0>();
        __syncthreads();
        const __half* Ab = Ah + cur * QKV_A_H;
        const __half* Bb = Bh + cur * QKV_B_H;
#pragma unroll
        for (int kk = 0; kk < 2; kk++) {
            HFragA a[2];
            HFragB b[4];
#pragma unroll
            for (int i = 0; i < 2; i++)
                wmma::load_matrix_sync(a[i], &Ab[(wr * 32 + i * 16) * QKA + kk * 16], QKA);
#pragma unroll
            for (int j = 0; j < 4; j++)
                wmma::load_matrix_sync(b[j], &Bb[(kk * 16) * QKB + wc * 64 + j * 16], QKB);
#pragma unroll
            for (int i = 0; i < 2; i++)
#pragma unroll
                for (int j = 0; j < 4; j++)
                    wmma::mma_sync(acc[i][j], a[i], b[j], acc[i][j]);
        }
        __syncthreads();
    }

    const int b = m0 >> 8, t0 = m0 & 255;
    float* mysc = scr + wid * 320;
#pragma unroll
    for (int i = 0; i < 2; i++)
#pragma unroll
        for (int j = 0; j < 4; j++) {
            int nm = nb + wc * 64 + j * 16;
            int h = nm >> 6, d0 = nm & 63;
            __half* op = outp + (size_t)((b * H_ + h) * T_ + t0 + wr * 32 + i * 16) * D_ + d0;
            frag2half(op, D_, acc[i][j], mysc, lane, oscale);
        }
}

// ---------------------------------------------------------------------------
// Kernel 2: causal attention. 256 thr (4x2 of 32x32 warp tiles), 128-row q
// tile, cp.async double-buffered K/V, fp32 S panel + in-place fp16 P.
// grid (2, 6, 64).
// ---------------------------------------------------------------------------
#define LDS_ 268
#define KVBUF_H (64*72)
#define ATTN_KV_OFF (128*72)                            // halves
#define ATTN_S_OFF  ((128*72 + 2*KVBUF_H)*2)            // bytes
#define ATTN_SCR_OFF (ATTN_S_OFF + 128*LDS_*4)
#define ATTN_SMEM_BYTES (ATTN_SCR_OFF + 8*320*4)

__global__ __launch_bounds__(256) void attn_kernel() {
    extern __shared__ char smc[];
    __half* Qh  = (__half*)smc;                    // 128 x 72
    __half* KV0 = (__half*)smc + ATTN_KV_OFF;      // buffer 0: 64 x 72
    __half* KV1 = KV0 + KVBUF_H;                   // buffer 1
    float*  Ss  = (float*)(smc + ATTN_S_OFF);      // 128 x LDS_
    __half* Hs  = (__half*)Ss;
    float*  scr = (float*)(smc + ATTN_SCR_OFF);

    const int qt = blockIdx.x;
    const int h  = blockIdx.y;
    const int b  = blockIdx.z;
    const size_t base = (size_t)((b * H_ + h) * T_) * D_;
    const __half* qp = g_qh + base + (size_t)qt * 128 * D_;
    const __half* kp = g_kh + base;
    const __half* vp = g_vh + base;

    const int tid = threadIdx.x;
    const int lane = tid & 31;
    const int wid = tid >> 5;
    const int wr = wid & 3;
    const int wc = wid >> 2;
    const int kbmax = 2 * qt + 1;
    const int L = (kbmax + 1) * 64;

    auto stageKV = [&](const __half* src, int kb, int buf) {
        __half* Dst = buf ? KV1 : KV0;
#pragma unroll
        for (int i = 0; i < 2; i++) {      // 64x64 halves = 512 uint4
            int idx = tid + i * 256;
            int r = idx >> 3, c = idx & 7;
            cp16(&Dst[r * 72 + c * 8], &src[(size_t)(kb * 64 + r) * D_ + c * 8]);
        }
    };

    // Q copy (group 1, together with K0)
#pragma unroll
    for (int i = 0; i < 4; i++) {
        int idx = tid + i * 256;
        int r = idx >> 3, c = idx & 7;
        cp16(&Qh[r * 72 + c * 8], &qp[(size_t)r * D_ + c * 8]);
    }
    stageKV(kp, 0, 0);
    cp_commit();

    // Phase 1: S = Q @ K^T
    for (int kb = 0; kb <= kbmax; kb++) {
        if (kb < kbmax) { stageKV(kp, kb + 1, (kb + 1) & 1); cp_commit(); cp_wait<1>(); }
        else cp_wait<0>();
        __syncthreads();
        const __half* Kb = (kb & 1) ? KV1 : KV0;

        HFragC sf[2][2];
#pragma unroll
        for (int i = 0; i < 2; i++)
#pragma unroll
            for (int j = 0; j < 2; j++) wmma::fill_fragment(sf[i][j], 0.0f);
#pragma unroll
        for (int kk = 0; kk < 4; kk++) {
            HFragA a[2];
            HFragBT bt[2];
#pragma unroll
            for (int i = 0; i < 2; i++)
                wmma::load_matrix_sync(a[i], &Qh[(wr * 32 + i * 16) * 72 + kk * 16], 72);
#pragma unroll
            for (int j = 0; j < 2; j++)
                wmma::load_matrix_sync(bt[j], &Kb[(wc * 32 + j * 16) * 72 + kk * 16], 72);
#pragma unroll
            for (int i = 0; i < 2; i++)
#pragma unroll
                for (int j = 0; j < 2; j++)
                    wmma::mma_sync(sf[i][j], a[i], bt[j], sf[i][j]);
        }
#pragma unroll
        for (int i = 0; i < 2; i++)
#pragma unroll
            for (int j = 0; j < 2; j++)
                wmma::store_matrix_sync(
                    &Ss[(wr * 32 + i * 16) * LDS_ + kb * 64 + wc * 32 + j * 16],
                    sf[i][j], LDS_, wmma::mem_row_major);
        __syncthreads();
    }

    // Softmax (fp32, register-held), P -> fp16 in place (16 rows/warp)
    const int nk = L >> 5;
    for (int rr = 0; rr < 16; rr++) {
        int r = wid * 16 + rr;
        int t = qt * 128 + r;
        float* Srow = &Ss[r * LDS_];
        float p[8];
        float mx = -1e30f;
        for (int k = 0; k < nk; k++) {
            int c = lane + 32 * k;
            float s = (c <= t) ? Srow[c] : -1e30f;
            p[k] = s;
            mx = fmaxf(mx, s);
        }
#pragma unroll
        for (int o = 16; o; o >>= 1) mx = fmaxf(mx, __shfl_xor_sync(~0u, mx, o));
        float sum = 0.f;
        for (int k = 0; k < nk; k++) {
            float e = __expf(p[k] - mx);
            p[k] = e;
            sum += e;
        }
#pragma unroll
        for (int o = 16; o; o >>= 1) sum += __shfl_xor_sync(~0u, sum, o);
        float inv = 1.f / sum;
        __half* Hrow = (__half*)Srow;
        for (int k = 0; k < nk; k++)
            Hrow[lane + 32 * k] = __float2half_rn(p[k] * inv);
    }
    __syncthreads();   // P visible to all warps; phase-1 K readers done

    // Phase 2: O = P @ V
    HFragC of[2][2];
#pragma unroll
    for (int i = 0; i < 2; i++)
#pragma unroll
        for (int j = 0; j < 2; j++) wmma::fill_fragment(of[i][j], 0.0f);

    stageKV(vp, 0, 0);
    cp_commit();

    for (int kb = 0; kb <= kbmax; kb++) {
        if (kb < kbmax) { stageKV(vp, kb + 1, (kb + 1) & 1); cp_commit(); cp_wait<1>(); }
        else cp_wait<0>();
        __syncthreads();
        const __half* Vb = (kb & 1) ? KV1 : KV0;
#pragma unroll
        for (int kk = 0; kk < 4; kk++) {
            HFragA a[2];
            HFragB bf[2];
#pragma unroll
            for (int i = 0; i < 2; i++)
                wmma::load_matrix_sync(
                    a[i], &Hs[(wr * 32 + i * 16) * (2 * LDS_) + kb * 64 + kk * 16],
                    2 * LDS_);
#pragma unroll
            for (int j = 0; j < 2; j++)
                wmma::load_matrix_sync(bf[j], &Vb[(kk * 16) * 72 + wc * 32 + j * 16], 72);
#pragma unroll
            for (int i = 0; i < 2; i++)
#pragma unroll
                for (int j = 0; j < 2; j++)
                    wmma::mma_sync(of[i][j], a[i], bf[j], of[i][j]);
        }
        __syncthreads();
    }

    __half* op = g_oh + base + (size_t)(qt * 128) * D_;
    float* mysc = scr + wid * 320;
#pragma unroll
    for (int i = 0; i < 2; i++)
#pragma unroll
        for (int j = 0; j < 2; j++)
            frag2half(op + (size_t)(wr * 32 + i * 16) * D_ + wc * 32 + j * 16,
                      D_, of[i][j], mysc, lane, 1.0f);
}

// ---------------------------------------------------------------------------
// Kernel 3: output projection. 128 thr (2x2 of 32x64 warp tiles),
// CTA 64 x 128, K-tile 32, cp.async double-buffered, bias in acc. grid (256, 3).
// ---------------------------------------------------------------------------
#define PA_H (64*QKA)
#define PB_H (32*QKB)
#define PROJ_SMEM_BYTES ((2*(PA_H + PB_H))*2)

__global__ __launch_bounds__(128) void proj_kernel(const float* __restrict__ bp,
                                                   float* __restrict__ out) {
    extern __shared__ __half smh[];
    __half* Ah = smh;               // [2][64][QKA]
    __half* Bh = smh + 2 * PA_H;    // [2][32][QKB]
    float* bias_s = (float*)smh;    // transient [16][136]

    const int tid = threadIdx.x;
    const int wid = tid >> 5;
    const int wr = wid & 1, wc = wid >> 1;
    const int m0 = blockIdx.x * 64;
    const int n0 = blockIdx.y * 128;
    const int b = m0 >> 8, t0 = m0 & 255;

#pragma unroll
    for (int i = 0; i < 4; i++) {
        int idx = tid + i * 128;
        int r = idx >> 5, c4 = idx & 31;
        *(float4*)&bias_s[r * 136 + c4 * 4] = *(const float4*)&bp[n0 + c4 * 4];
    }
    __syncthreads();

    HFragC acc[2][4];
#pragma unroll
    for (int i = 0; i < 2; i++)
#pragma unroll
        for (int j = 0; j < 4; j++)
            wmma::load_matrix_sync(acc[i][j], &bias_s[wc * 64 + j * 16], 136,
                                   wmma::mem_row_major);
    __syncthreads();

    auto stage = [&](int k0, int buf) {
        __half* Ab = Ah + buf * PA_H;
        __half* Bb = Bh + buf * PB_H;
        const int hh = k0 >> 6, d0 = k0 & 63;
#pragma unroll
        for (int i = 0; i < 2; i++) {      // A: 64x32 halves = 256 uint4
            int idx = tid + i * 128;
            int r = idx >> 2, c = idx & 3;
            cp16(&Ab[r * QKA + c * 8],
                 &g_oh[(size_t)((b * H_ + hh) * T_ + t0 + r) * D_ + d0 + c * 8]);
        }
#pragma unroll
        for (int i = 0; i < 4; i++) {      // B: 32x128 halves = 512 uint4
            int idx = tid + i * 128;
            int r = idx >> 4, c = idx & 15;
            cp16(&Bb[r * QKB + c * 8], &g_wph[(size_t)(k0 + r) * C_ + n0 + c * 8]);
        }
    };

    stage(0, 0);
    cp_commit();

    for (int kt = 0; kt < 12; kt++) {
        const int cur = kt & 1;
        if (kt < 11) { stage((kt + 1) * 32, cur ^ 1); cp_commit(); cp_wait<1>(); }
        else cp_wait<0>();
        __syncthreads();
        const __half* Ab = Ah + cur * PA_H;
        const __half* Bb = Bh + cur * PB_H;
#pragma unroll
        for (int kk = 0; kk < 2; kk++) {
            HFragA a[2];
            HFragB bf[4];
#pragma unroll
            for (int i = 0; i < 2; i++)
                wmma::load_matrix_sync(a[i], &Ab[(wr * 32 + i * 16) * QKA + kk * 16], QKA);
#pragma unroll
            for (int j = 0; j < 4; j++)
                wmma::load_matrix_sync(bf[j], &Bb[(kk * 16) * QKB + wc * 64 + j * 16], QKB);
#pragma unroll
            for (int i = 0; i < 2; i++)
#pragma unroll
                for (int j = 0; j < 4; j++)
                    wmma::mma_sync(acc[i][j], a[i], bf[j], acc[i][j]);
        }
        __syncthreads();
    }

#pragma unroll
    for (int i = 0; i < 2; i++)
#pragma unroll
        for (int j = 0; j < 4; j++) {
            float* op = out + (size_t)(m0 + wr * 32 + i * 16) * C_ + n0 + wc * 64 + j * 16;
            wmma::store_matrix_sync(op, acc[i][j], C_, wmma::mem_row_major);
        }
}

// ---------------------------------------------------------------------------
extern "C" void kernel_launch(void* const* d_in, const int* in_sizes, int n_in,
                              void* d_out, int out_size) {
    const float* x  = (const float*)d_in[0];
    const float* Wq = (const float*)d_in[1];
    const float* Wk = (const float*)d_in[2];
    const float* Wv = (const float*)d_in[3];
    const float* Wp = (const float*)d_in[4];
    const float* bp = (const float*)d_in[5];
    float* out = (float*)d_out;

    cudaFuncSetAttribute(qkv_kernel, cudaFuncAttributeMaxDynamicSharedMemorySize,
                         QKV_SMEM_BYTES);
    cudaFuncSetAttribute(attn_kernel, cudaFuncAttributeMaxDynamicSharedMemorySize,
                         ATTN_SMEM_BYTES);
    cudaFuncSetAttribute(proj_kernel, cudaFuncAttributeMaxDynamicSharedMemorySize,
                         PROJ_SMEM_BYTES);

    prep_kernel<<<(NTOT4 + 255)/256, 256>>>((const float4*)x, (const float4*)Wq,
                                            (const float4*)Wk, (const float4*)Wv,
                                            (const float4*)Wp);
    qkv_kernel<<<dim3(M_ / 128, 9), 256, QKV_SMEM_BYTES>>>();
    attn_kernel<<<dim3(T_ / 128, H_, B_), 256, ATTN_SMEM_BYTES>>>();
    proj_kernel<<<dim3(M_ / 64, C_ / 128), 128, PROJ_SMEM_BYTES>>>(bp, out);
}